// round 2
// baseline (speedup 1.0000x reference)
#include <cuda_runtime.h>
#include <math.h>

#define NT 256   // ntheta
#define NP 512   // nphi
#define NC 32    // channels
#define NL 128   // L

typedef unsigned long long u64;

// ---------- packed f32x2 helpers (sm_103a FFMA2) ----------
__device__ __forceinline__ u64 pk2(float a, float b) {
    u64 r; asm("mov.b64 %0,{%1,%2};" : "=l"(r) : "f"(a), "f"(b)); return r;
}
__device__ __forceinline__ float2 upk(u64 v) {
    float2 f; asm("mov.b64 {%0,%1},%2;" : "=f"(f.x), "=f"(f.y) : "l"(v)); return f;
}
__device__ __forceinline__ u64 fma2(u64 a, u64 b, u64 c) {
    u64 d; asm("fma.rn.f32x2 %0,%1,%2,%3;" : "=l"(d) : "l"(a), "l"(b), "l"(c)); return d;
}

// ---------- static device scratch (no allocations allowed) ----------
__device__ u64 g_F  [NT][NL][NC];   // (re,im) of F[t][m][c], wq[t]*2pi/512 folded in
__device__ u64 g_flm[NL][NL][NC];   // [m][l][c] (re,im); valid only l>=m
__device__ u64 g_uv [NL][NL][NC];   // [m][l][o] (u,v);    valid only l>=m
__device__ u64 g_AB [NT][NL][NC];   // [t][m][o] (A,B)

// ============================================================
// K1: forward DFT over phi. F[t][m][c] = sum_p x[t][p][c] e^{-2pi i m p/512}
// grid 256 (t), block 256 = 128 m x 2 c-groups (16 c each)
// ============================================================
__global__ __launch_bounds__(256) void k1_dft(const float* __restrict__ x,
                                              const float* __restrict__ wq) {
    __shared__ float4 sx[256][8];   // 256 p x 32 c floats = 32 KB
    const int t   = blockIdx.x;
    const int tid = threadIdx.x;
    const int m   = tid & 127;
    const int cg  = tid >> 7;       // 0..1 -> channels cg*16 .. cg*16+15

    u64 aR[8], aI[8];
#pragma unroll
    for (int k = 0; k < 8; k++) { aR[k] = 0ull; aI[k] = 0ull; }

    // per-step rotation e^{-i*pi*m/256}
    float sd, cd;
    sincosf(-(float)M_PI / 256.0f * (float)m, &sd, &cd);

    for (int ch = 0; ch < 2; ch++) {
        __syncthreads();
        const float4* gx = (const float4*)(x + ((size_t)t * NP + (size_t)ch * 256) * NC);
        for (int i = tid; i < 2048; i += 256) ((float4*)sx)[i] = gx[i];
        __syncthreads();

        // chunk start: theta = -2pi*m*(256*ch)/512 = -pi*m*ch -> exact
        float rc = (ch == 0) ? 1.0f : ((m & 1) ? -1.0f : 1.0f);
        float rs = 0.0f;

        for (int pp = 0; pp < 256; pp++) {
            u64 cc = pk2(rc, rc);
            u64 ss = pk2(rs, rs);
            const ulonglong2* row = (const ulonglong2*)&sx[pp][cg * 4];
#pragma unroll
            for (int k = 0; k < 4; k++) {
                ulonglong2 v = row[k];          // 2 channel-pairs packed
                aR[2 * k]     = fma2(v.x, cc, aR[2 * k]);
                aI[2 * k]     = fma2(v.x, ss, aI[2 * k]);
                aR[2 * k + 1] = fma2(v.y, cc, aR[2 * k + 1]);
                aI[2 * k + 1] = fma2(v.y, ss, aI[2 * k + 1]);
            }
            float nc = rc * cd - rs * sd;
            float ns = rs * cd + rc * sd;
            rc = nc; rs = ns;
        }
    }

    const float scale = wq[t] * (2.0f * (float)M_PI / 512.0f);
#pragma unroll
    for (int k = 0; k < 8; k++) {
        float2 r = upk(aR[k]);
        float2 i2 = upk(aI[k]);
        int c = cg * 16 + 2 * k;
        g_F[t][m][c]     = pk2(r.x * scale, i2.x * scale);
        g_F[t][m][c + 1] = pk2(r.y * scale, i2.y * scale);
    }
}

// ============================================================
// K2: Legendre analysis. flm[m][l][c] = sum_t P[l][127+m][t] * F[t][m][c]
// grid 128 (m), block 256 = 8 warps; warp handles 4 l's per pass, lane = c
// ============================================================
__global__ __launch_bounds__(256) void k2_analysis(const float* __restrict__ leg) {
    const int m    = blockIdx.x;
    const int w    = threadIdx.x >> 5;
    const int lane = threadIdx.x & 31;
    const int nl   = NL - m;

    for (int li = w * 4; li < nl; li += 32) {
        u64 acc[4] = {0ull, 0ull, 0ull, 0ull};
        const int lmax = min(4, nl - li);
        const float* bp[4];
#pragma unroll
        for (int k = 0; k < 4; k++) {
            int l = m + li + k; if (l > 127) l = 127;
            bp[k] = leg + ((size_t)l * 255 + (127 + m)) * NT;
        }
#pragma unroll 4
        for (int t = 0; t < NT; t++) {
            u64 f = g_F[t][m][lane];
#pragma unroll
            for (int k = 0; k < 4; k++) {
                float b = __ldg(bp[k] + t);
                acc[k] = fma2(pk2(b, b), f, acc[k]);
            }
        }
        for (int k = 0; k < lmax; k++)
            g_flm[m][m + li + k][lane] = acc[k];
    }
}

// ============================================================
// K3: channel mix, +m/-m weight pairs fused.
//   u[o] = sum_c fr*S + fi*D,  v[o] = sum_c fr*D - fi*S
//   S = wr(+m)+wr(-m), D = wi(-m)-wi(+m);  m=0: S=wr, D=-wi
// grid (128 l, 128 m), block 256 = 8 warps x (4 c each), lane = o
// ============================================================
__global__ __launch_bounds__(256) void k3_mix(const float* __restrict__ Wr,
                                              const float* __restrict__ Wi) {
    const int l = blockIdx.x;
    const int m = blockIdx.y;
    if (l < m) return;

    __shared__ float2 sf[32];
    __shared__ float2 red[8][32];
    const int tid = threadIdx.x, w = tid >> 5, lane = tid & 31;

    if (tid < 32) sf[tid] = ((const float2*)&g_flm[m][l][0])[tid];
    __syncthreads();

    const size_t bp = ((size_t)l * 255 + (127 + m)) * 1024;
    const size_t bn = ((size_t)l * 255 + (127 - m)) * 1024;

    float U = 0.0f, V = 0.0f;
#pragma unroll
    for (int k = 0; k < 4; k++) {
        const int c = w * 4 + k;
        const size_t op = bp + (size_t)c * 32 + lane;
        float wr = __ldcs(Wr + op);
        float wi = __ldcs(Wi + op);
        float S, D;
        if (m) {
            const size_t on = bn + (size_t)c * 32 + lane;
            S = wr + __ldcs(Wr + on);
            D = __ldcs(Wi + on) - wi;
        } else {
            S = wr; D = -wi;
        }
        const float fr = sf[c].x, fi = sf[c].y;
        U += fr * S; U += fi * D;
        V += fr * D; V -= fi * S;
    }
    red[w][lane] = make_float2(U, V);
    __syncthreads();
    if (w == 0) {
        float2 a = red[0][lane];
#pragma unroll
        for (int k = 1; k < 8; k++) { a.x += red[k][lane].x; a.y += red[k][lane].y; }
        g_uv[m][l][lane] = pk2(a.x, a.y);
    }
}

// ============================================================
// K4: Legendre synthesis. (A,B)[t][m][o] = sum_{l>=m} P[l][127+m][t] * (u,v)[m][l][o]
// grid (128 m, 8 t-groups of 32), block 256 = 8 warps x 4 t, lane = o
// ============================================================
__global__ __launch_bounds__(256) void k4_synth(const float* __restrict__ leg) {
    const int m  = blockIdx.x;
    const int tg = blockIdx.y;
    const int nl = NL - m;

    __shared__ u64  suv[128][32];   // 32 KB
    __shared__ float sP[128][32];   // 16 KB
    const int tid = threadIdx.x, w = tid >> 5, lane = tid & 31;

    for (int i = tid; i < nl * 32; i += 256)
        ((u64*)suv)[i] = ((const u64*)&g_uv[m][m][0])[i];
    for (int i = tid; i < nl * 32; i += 256) {
        const int il = i >> 5, tt = i & 31;
        ((float*)sP)[i] = leg[((size_t)(m + il) * 255 + (127 + m)) * NT + tg * 32 + tt];
    }
    __syncthreads();

    u64 acc[4] = {0ull, 0ull, 0ull, 0ull};
    const int tb = w * 4;
    for (int il = 0; il < nl; il++) {
        const u64 uvv = suv[il][lane];
#pragma unroll
        for (int j = 0; j < 4; j++) {
            const float p = sP[il][tb + j];
            acc[j] = fma2(pk2(p, p), uvv, acc[j]);
        }
    }
    const int t0 = tg * 32 + tb;
#pragma unroll
    for (int j = 0; j < 4; j++)
        g_AB[t0 + j][m][lane] = acc[j];
}

// ============================================================
// K5: inverse transform. out[o][t][p] = sum_{m=0..127} A cos(2pi m p/512) + B sin(...)
// grid 256 (t), block 512 (p)
// ============================================================
__global__ __launch_bounds__(512, 1) void k5_idft(float* __restrict__ out) {
    __shared__ u64 sAB[128][32];    // 32 KB
    const int t = blockIdx.x;
    const int p = threadIdx.x;

    for (int i = p; i < 128 * 32; i += 512)
        ((u64*)sAB)[i] = ((const u64*)&g_AB[t][0][0])[i];
    __syncthreads();

    u64 acc[32];
#pragma unroll
    for (int o = 0; o < 32; o++) acc[o] = 0ull;

    float sd, cd;
    sincosf(((float)M_PI / 256.0f) * (float)p, &sd, &cd);
    float rc = 1.0f, rs = 0.0f;

    for (int m = 0; m < 128; m++) {
        const u64 cs = pk2(rc, rs);
        const ulonglong2* row = (const ulonglong2*)&sAB[m][0];
#pragma unroll
        for (int k = 0; k < 16; k++) {
            ulonglong2 v = row[k];
            acc[2 * k]     = fma2(v.x, cs, acc[2 * k]);
            acc[2 * k + 1] = fma2(v.y, cs, acc[2 * k + 1]);
        }
        float nc = rc * cd - rs * sd;
        float ns = rs * cd + rc * sd;
        rc = nc; rs = ns;
    }

#pragma unroll
    for (int o = 0; o < 32; o++) {
        float2 r = upk(acc[o]);
        out[((size_t)o * NT + t) * NP + p] = r.x + r.y;
    }
}

// ============================================================
extern "C" void kernel_launch(void* const* d_in, const int* in_sizes, int n_in,
                              void* d_out, int out_size) {
    const float* x   = (const float*)d_in[0];
    const float* Wr  = (const float*)d_in[1];
    const float* Wi  = (const float*)d_in[2];
    const float* leg = (const float*)d_in[3];
    const float* wq  = (const float*)d_in[4];
    float* out = (float*)d_out;

    k1_dft<<<256, 256>>>(x, wq);
    k2_analysis<<<128, 256>>>(leg);
    k3_mix<<<dim3(128, 128), 256>>>(Wr, Wi);
    k4_synth<<<dim3(128, 8), 256>>>(leg);
    k5_idft<<<256, 512>>>(out);
}

// round 3
// speedup vs baseline: 1.7004x; 1.7004x over previous
#include <cuda_runtime.h>
#include <math.h>

#define NT 256   // ntheta
#define NP 512   // nphi
#define NC 32    // channels
#define NL 128   // L

typedef unsigned long long u64;

// ---------- packed f32x2 helpers (sm_103a FFMA2) ----------
__device__ __forceinline__ u64 pk2(float a, float b) {
    u64 r; asm("mov.b64 %0,{%1,%2};" : "=l"(r) : "f"(a), "f"(b)); return r;
}
__device__ __forceinline__ float2 upk(u64 v) {
    float2 f; asm("mov.b64 {%0,%1},%2;" : "=f"(f.x), "=f"(f.y) : "l"(v)); return f;
}
__device__ __forceinline__ u64 fma2(u64 a, u64 b, u64 c) {
    u64 d; asm("fma.rn.f32x2 %0,%1,%2,%3;" : "=l"(d) : "l"(a), "l"(b), "l"(c)); return d;
}
__device__ __forceinline__ u64 mul2(u64 a, u64 b) {
    u64 d; asm("mul.rn.f32x2 %0,%1,%2;" : "=l"(d) : "l"(a), "l"(b)); return d;
}

// ---------- static device scratch ----------
__device__ u64 g_F  [NT][NL][NC];   // (re,im) of F[t][m][c], wq*2pi/512 folded in
__device__ u64 g_flm[NL][NL][NC];   // [m][l][c]; valid only l>=m
__device__ u64 g_uv [NL][NL][NC];   // [m][l][o]; valid only l>=m
__device__ u64 g_AB [NT][NL][NC];   // [t][m][o] (A,B)

// ============================================================
// K1: forward DFT over phi, radix-2 folded (q and q+256 share twiddles).
// grid 256 (t), block 128 (m). dynamic smem 64KB: ype/ymo[256][16] u64.
// warp0,1 -> even m; warp2,3 -> odd m (uniform smem row per warp).
// ============================================================
__global__ __launch_bounds__(128) void k1_dft(const float* __restrict__ x,
                                              const float* __restrict__ wq) {
    extern __shared__ u64 sm1[];
    u64* ype = sm1;              // [256][16]
    u64* ymo = sm1 + 256 * 16;   // [256][16]

    const int t   = blockIdx.x;
    const int tid = threadIdx.x;
    const int w   = tid >> 5;
    const int lane = tid & 31;
    const int par = w >> 1;                       // 0: even m, 1: odd m
    const int m   = 2 * (((w & 1) << 5) + lane) + par;

    // ---- stage parity-combined, scale-folded rows ----
    {
        const float s = wq[t] * (2.0f * (float)M_PI / 512.0f);
        const float4* x4 = (const float4*)(x + (size_t)t * NP * NC);
        for (int i = tid; i < 2048; i += 128) {
            float4 a = x4[i];
            float4 b = x4[i + 2048];
            const int p = i >> 3, j = i & 7;
            ype[p * 16 + j * 2]     = pk2((a.x + b.x) * s, (a.y + b.y) * s);
            ype[p * 16 + j * 2 + 1] = pk2((a.z + b.z) * s, (a.w + b.w) * s);
            ymo[p * 16 + j * 2]     = pk2((a.x - b.x) * s, (a.y - b.y) * s);
            ymo[p * 16 + j * 2 + 1] = pk2((a.z - b.z) * s, (a.w - b.w) * s);
        }
    }
    __syncthreads();

    const u64* yrow = par ? ymo : ype;

    // packed rotation state: e^{-i*pi*m*q/256}
    float sd, cd;
    sincosf(-(float)M_PI / 256.0f * (float)m, &sd, &cd);
    u64 CDD = pk2(cd, cd), SDD = pk2(sd, sd), NSD = pk2(-sd, -sd);
    u64 CC = pk2(1.0f, 1.0f), SS = pk2(0.0f, 0.0f);

    u64 aR[16], aI[16];
#pragma unroll
    for (int k = 0; k < 16; k++) { aR[k] = 0ull; aI[k] = 0ull; }

#pragma unroll 2
    for (int q = 0; q < 256; q++) {
        const ulonglong2* row = (const ulonglong2*)(yrow + q * 16);
#pragma unroll
        for (int k = 0; k < 8; k++) {
            ulonglong2 v = row[k];
            aR[2 * k]     = fma2(v.x, CC, aR[2 * k]);
            aI[2 * k]     = fma2(v.x, SS, aI[2 * k]);
            aR[2 * k + 1] = fma2(v.y, CC, aR[2 * k + 1]);
            aI[2 * k + 1] = fma2(v.y, SS, aI[2 * k + 1]);
        }
        u64 t1 = mul2(SS, NSD);
        u64 nC = fma2(CC, CDD, t1);
        u64 t2 = mul2(CC, SDD);
        SS = fma2(SS, CDD, t2);
        CC = nC;
    }

    ulonglong2* fout = (ulonglong2*)&g_F[t][m][0];
#pragma unroll
    for (int k = 0; k < 16; k++) {
        float2 r = upk(aR[k]), i2 = upk(aI[k]);
        fout[k] = make_ulonglong2(pk2(r.x, i2.x), pk2(r.y, i2.y));
    }
}

// ============================================================
// K2: Legendre analysis, theta-parity folded (t < 128).
// flm[l] = sum_{t<128} P[l][t] * (F[t] + (-1)^{l+m} F[255-t])
// grid 128 (m), block 256. dynamic smem 64KB: Fp/Fm[128][32] u64.
// parity of (l+m) for l=m+li+k with li even is just k&1 (static).
// ============================================================
__global__ __launch_bounds__(256) void k2_analysis(const float* __restrict__ leg) {
    extern __shared__ u64 sm2[];
    u64* Fp = sm2;               // [128][32]
    u64* Fm = sm2 + 128 * 32;

    const int m    = blockIdx.x;
    const int tid  = threadIdx.x;
    const int w    = tid >> 5;
    const int lane = tid & 31;
    const int nl   = NL - m;

    for (int i = tid; i < 128 * 32; i += 256) {
        const int t = i >> 5, c = i & 31;
        float2 a = upk(g_F[t][m][c]);
        float2 b = upk(g_F[255 - t][m][c]);
        Fp[i] = pk2(a.x + b.x, a.y + b.y);
        Fm[i] = pk2(a.x - b.x, a.y - b.y);
    }
    __syncthreads();

    for (int li = w * 4; li < nl; li += 32) {
        u64 acc[4] = {0ull, 0ull, 0ull, 0ull};
        const int lmax = min(4, nl - li);
        const float* bp[4];
#pragma unroll
        for (int k = 0; k < 4; k++) {
            int l = m + li + k; if (l > 127) l = 127;
            bp[k] = leg + ((size_t)l * 255 + (127 + m)) * NT;
        }
#pragma unroll 2
        for (int t = 0; t < 128; t++) {
            u64 fp = Fp[t * 32 + lane];
            u64 fm = Fm[t * 32 + lane];
#pragma unroll
            for (int k = 0; k < 4; k++) {
                float b = __ldg(bp[k] + t);
                acc[k] = fma2(pk2(b, b), (k & 1) ? fm : fp, acc[k]);
            }
        }
        for (int k = 0; k < lmax; k++)
            g_flm[m][m + li + k][lane] = acc[k];
    }
}

// ============================================================
// K3: channel mix, +m/-m weight pairs fused (DRAM-bound stream).
// ============================================================
__global__ __launch_bounds__(256) void k3_mix(const float* __restrict__ Wr,
                                              const float* __restrict__ Wi) {
    const int l = blockIdx.x;
    const int m = blockIdx.y;
    if (l < m) return;

    __shared__ float2 sf[32];
    __shared__ float2 red[8][32];
    const int tid = threadIdx.x, w = tid >> 5, lane = tid & 31;

    if (tid < 32) sf[tid] = ((const float2*)&g_flm[m][l][0])[tid];
    __syncthreads();

    const size_t bp = ((size_t)l * 255 + (127 + m)) * 1024;
    const size_t bn = ((size_t)l * 255 + (127 - m)) * 1024;

    float U = 0.0f, V = 0.0f;
#pragma unroll
    for (int k = 0; k < 4; k++) {
        const int c = w * 4 + k;
        const size_t op = bp + (size_t)c * 32 + lane;
        float wr = __ldcs(Wr + op);
        float wi = __ldcs(Wi + op);
        float S, D;
        if (m) {
            const size_t on = bn + (size_t)c * 32 + lane;
            S = wr + __ldcs(Wr + on);
            D = __ldcs(Wi + on) - wi;
        } else {
            S = wr; D = -wi;
        }
        const float fr = sf[c].x, fi = sf[c].y;
        U += fr * S; U += fi * D;
        V += fr * D; V -= fi * S;
    }
    red[w][lane] = make_float2(U, V);
    __syncthreads();
    if (w == 0) {
        float2 a = red[0][lane];
#pragma unroll
        for (int k = 1; k < 8; k++) { a.x += red[k][lane].x; a.y += red[k][lane].y; }
        g_uv[m][l][lane] = pk2(a.x, a.y);
    }
}

// ============================================================
// K4: Legendre synthesis, theta-parity folded: t<128 produces t and 255-t.
// Parity of (l+m) for l=m+il is il&1 -> static E/O accumulators.
// grid (128 m, 4 tg), block 256 (8 warps x 4 t, lane=o).
// dynamic smem 64KB: suv[128][32] u64, sPd[128][32] u64 (P duplicated).
// ============================================================
__global__ __launch_bounds__(256) void k4_synth(const float* __restrict__ leg) {
    extern __shared__ u64 sm4[];
    u64* suv = sm4;              // [128][32]
    u64* sPd = sm4 + 128 * 32;   // [128][32]

    const int m   = blockIdx.x;
    const int tg  = blockIdx.y;
    const int nl  = NL - m;
    const int nlp = (nl + 1) & ~1;   // zero-padded to even
    const int tid = threadIdx.x, w = tid >> 5, lane = tid & 31;

    for (int i = tid; i < nlp * 32; i += 256)
        suv[i] = (i < nl * 32) ? ((const u64*)&g_uv[m][m][0])[i] : 0ull;
    for (int i = tid; i < nlp * 32; i += 256) {
        const int il = i >> 5, tt = i & 31;
        float v = (il < nl) ? leg[((size_t)(m + il) * 255 + (127 + m)) * NT + tg * 32 + tt] : 0.0f;
        sPd[i] = pk2(v, v);
    }
    __syncthreads();

    u64 E[4] = {0ull, 0ull, 0ull, 0ull};
    u64 O[4] = {0ull, 0ull, 0ull, 0ull};
    const int tb = w * 4;

    for (int il = 0; il < nlp; il += 2) {
        const u64 uv0 = suv[il * 32 + lane];
        const u64 uv1 = suv[(il + 1) * 32 + lane];
        const ulonglong2* p0 = (const ulonglong2*)(sPd + il * 32 + tb);
        const ulonglong2* p1 = (const ulonglong2*)(sPd + (il + 1) * 32 + tb);
        ulonglong2 pa = p0[0], pb = p0[1];
        ulonglong2 pc = p1[0], pd = p1[1];
        E[0] = fma2(pa.x, uv0, E[0]);
        E[1] = fma2(pa.y, uv0, E[1]);
        E[2] = fma2(pb.x, uv0, E[2]);
        E[3] = fma2(pb.y, uv0, E[3]);
        O[0] = fma2(pc.x, uv1, O[0]);
        O[1] = fma2(pc.y, uv1, O[1]);
        O[2] = fma2(pd.x, uv1, O[2]);
        O[3] = fma2(pd.y, uv1, O[3]);
    }

#pragma unroll
    for (int j = 0; j < 4; j++) {
        const int t = tg * 32 + tb + j;
        float2 e = upk(E[j]), o2 = upk(O[j]);
        g_AB[t][m][lane]       = pk2(e.x + o2.x, e.y + o2.y);
        g_AB[255 - t][m][lane] = pk2(e.x - o2.x, e.y - o2.y);
    }
}

// ============================================================
// K5: inverse transform, even/odd-m folded: p<256 produces p and p+256.
// grid 256 (t), block 512 = 256 p x 2 o-groups (16 o each).
// ============================================================
__global__ __launch_bounds__(512, 1) void k5_idft(float* __restrict__ out) {
    __shared__ u64 sAB[128 * 32];
    const int t   = blockIdx.x;
    const int tid = threadIdx.x;
    const int p   = tid & 255;
    const int ob  = (tid >> 8) * 16;

    for (int i = tid; i < 128 * 32; i += 512)
        sAB[i] = ((const u64*)&g_AB[t][0][0])[i];
    __syncthreads();

    u64 E[16], O[16];
#pragma unroll
    for (int k = 0; k < 16; k++) { E[k] = 0ull; O[k] = 0ull; }

    float sd, cd;
    sincosf(((float)M_PI / 256.0f) * (float)p, &sd, &cd);
    u64 CDD = pk2(cd, cd);
    u64 P1 = pk2(-sd, sd), P2 = pk2(sd, -sd);
    u64 cs = pk2(1.0f, 0.0f), sc = pk2(0.0f, 1.0f);

    for (int m = 0; m < 128; m += 2) {
        const ulonglong2* r0 = (const ulonglong2*)(sAB + m * 32 + ob);
#pragma unroll
        for (int k = 0; k < 8; k++) {
            ulonglong2 v = r0[k];
            E[2 * k]     = fma2(v.x, cs, E[2 * k]);
            E[2 * k + 1] = fma2(v.y, cs, E[2 * k + 1]);
        }
        { u64 t1 = mul2(sc, P1); u64 nc = fma2(cs, CDD, t1);
          u64 t2 = mul2(cs, P2); sc = fma2(sc, CDD, t2); cs = nc; }

        const ulonglong2* r1 = (const ulonglong2*)(sAB + (m + 1) * 32 + ob);
#pragma unroll
        for (int k = 0; k < 8; k++) {
            ulonglong2 v = r1[k];
            O[2 * k]     = fma2(v.x, cs, O[2 * k]);
            O[2 * k + 1] = fma2(v.y, cs, O[2 * k + 1]);
        }
        { u64 t1 = mul2(sc, P1); u64 nc = fma2(cs, CDD, t1);
          u64 t2 = mul2(cs, P2); sc = fma2(sc, CDD, t2); cs = nc; }
    }

#pragma unroll
    for (int k = 0; k < 16; k++) {
        float2 e = upk(E[k]), o2 = upk(O[k]);
        const float ev = e.x + e.y, ov = o2.x + o2.y;
        const size_t base = ((size_t)(ob + k) * NT + t) * NP;
        out[base + p]       = ev + ov;
        out[base + p + 256] = ev - ov;
    }
}

// ============================================================
extern "C" void kernel_launch(void* const* d_in, const int* in_sizes, int n_in,
                              void* d_out, int out_size) {
    const float* x   = (const float*)d_in[0];
    const float* Wr  = (const float*)d_in[1];
    const float* Wi  = (const float*)d_in[2];
    const float* leg = (const float*)d_in[3];
    const float* wq  = (const float*)d_in[4];
    float* out = (float*)d_out;

    cudaFuncSetAttribute(k1_dft,      cudaFuncAttributeMaxDynamicSharedMemorySize, 65536);
    cudaFuncSetAttribute(k2_analysis, cudaFuncAttributeMaxDynamicSharedMemorySize, 65536);
    cudaFuncSetAttribute(k4_synth,    cudaFuncAttributeMaxDynamicSharedMemorySize, 65536);

    k1_dft<<<256, 128, 65536>>>(x, wq);
    k2_analysis<<<128, 256, 65536>>>(leg);
    k3_mix<<<dim3(128, 128), 256>>>(Wr, Wi);
    k4_synth<<<dim3(128, 4), 256, 65536>>>(leg);
    k5_idft<<<256, 512>>>(out);
}

// round 4
// speedup vs baseline: 1.7648x; 1.0379x over previous
#include <cuda_runtime.h>
#include <math.h>

#define NT 256   // ntheta
#define NP 512   // nphi
#define NC 32    // channels
#define NL 128   // L

typedef unsigned long long u64;

// ---------- packed f32x2 helpers (sm_103a FFMA2) ----------
__device__ __forceinline__ u64 pk2(float a, float b) {
    u64 r; asm("mov.b64 %0,{%1,%2};" : "=l"(r) : "f"(a), "f"(b)); return r;
}
__device__ __forceinline__ float2 upk(u64 v) {
    float2 f; asm("mov.b64 {%0,%1},%2;" : "=f"(f.x), "=f"(f.y) : "l"(v)); return f;
}
__device__ __forceinline__ u64 fma2(u64 a, u64 b, u64 c) {
    u64 d; asm("fma.rn.f32x2 %0,%1,%2,%3;" : "=l"(d) : "l"(a), "l"(b), "l"(c)); return d;
}
__device__ __forceinline__ u64 mul2(u64 a, u64 b) {
    u64 d; asm("mul.rn.f32x2 %0,%1,%2;" : "=l"(d) : "l"(a), "l"(b)); return d;
}

// ---------- static device scratch ----------
__device__ u64 g_F  [NT][NL][NC];   // (re,im) of F[t][m][c], wq*2pi/512 folded in
__device__ u64 g_flm[NL][NL][NC];   // [m][l][c]; valid only l>=m
__device__ u64 g_uv [NL][NL][NC];   // [m][l][o]; valid only l>=m
__device__ u64 g_AB [NT][NL][NC];   // [t][m][o] (A,B)

// ============================================================
// K1: forward DFT over phi, radix-2 folded (q and q+256 share twiddles).
// grid 256 (t), block 128 (m). dynamic smem 64KB: ype/ymo[256][16] u64.
// warp0,1 -> even m; warp2,3 -> odd m (uniform smem row per warp).
// ============================================================
__global__ __launch_bounds__(128) void k1_dft(const float* __restrict__ x,
                                              const float* __restrict__ wq) {
    extern __shared__ u64 sm1[];
    u64* ype = sm1;              // [256][16]
    u64* ymo = sm1 + 256 * 16;   // [256][16]

    const int t   = blockIdx.x;
    const int tid = threadIdx.x;
    const int w   = tid >> 5;
    const int lane = tid & 31;
    const int par = w >> 1;                       // 0: even m, 1: odd m
    const int m   = 2 * (((w & 1) << 5) + lane) + par;

    // ---- stage parity-combined, scale-folded rows ----
    {
        const float s = wq[t] * (2.0f * (float)M_PI / 512.0f);
        const float4* x4 = (const float4*)(x + (size_t)t * NP * NC);
        for (int i = tid; i < 2048; i += 128) {
            float4 a = x4[i];
            float4 b = x4[i + 2048];
            const int p = i >> 3, j = i & 7;
            ype[p * 16 + j * 2]     = pk2((a.x + b.x) * s, (a.y + b.y) * s);
            ype[p * 16 + j * 2 + 1] = pk2((a.z + b.z) * s, (a.w + b.w) * s);
            ymo[p * 16 + j * 2]     = pk2((a.x - b.x) * s, (a.y - b.y) * s);
            ymo[p * 16 + j * 2 + 1] = pk2((a.z - b.z) * s, (a.w - b.w) * s);
        }
    }
    __syncthreads();

    const u64* yrow = par ? ymo : ype;

    // packed rotation state: e^{-i*pi*m*q/256}
    float sd, cd;
    sincosf(-(float)M_PI / 256.0f * (float)m, &sd, &cd);
    u64 CDD = pk2(cd, cd), SDD = pk2(sd, sd), NSD = pk2(-sd, -sd);
    u64 CC = pk2(1.0f, 1.0f), SS = pk2(0.0f, 0.0f);

    u64 aR[16], aI[16];
#pragma unroll
    for (int k = 0; k < 16; k++) { aR[k] = 0ull; aI[k] = 0ull; }

#pragma unroll 4
    for (int q = 0; q < 256; q++) {
        const ulonglong2* row = (const ulonglong2*)(yrow + q * 16);
#pragma unroll
        for (int k = 0; k < 8; k++) {
            ulonglong2 v = row[k];
            aR[2 * k]     = fma2(v.x, CC, aR[2 * k]);
            aI[2 * k]     = fma2(v.x, SS, aI[2 * k]);
            aR[2 * k + 1] = fma2(v.y, CC, aR[2 * k + 1]);
            aI[2 * k + 1] = fma2(v.y, SS, aI[2 * k + 1]);
        }
        u64 t1 = mul2(SS, NSD);
        u64 nC = fma2(CC, CDD, t1);
        u64 t2 = mul2(CC, SDD);
        SS = fma2(SS, CDD, t2);
        CC = nC;
    }

    ulonglong2* fout = (ulonglong2*)&g_F[t][m][0];
#pragma unroll
    for (int k = 0; k < 16; k++) {
        float2 r = upk(aR[k]), i2 = upk(aI[k]);
        fout[k] = make_ulonglong2(pk2(r.x, i2.x), pk2(r.y, i2.y));
    }
}

// ============================================================
// K2: Legendre analysis, theta-parity folded (t < 128), m-pair balanced:
// block mp handles m=mp and m=127-mp (total l-work constant = 129).
// grid 64, block 256. dynamic smem 64KB: Fp/Fm[128][32] u64.
// ============================================================
__global__ __launch_bounds__(256) void k2_analysis(const float* __restrict__ leg) {
    extern __shared__ u64 sm2[];
    u64* Fp = sm2;               // [128][32]
    u64* Fm = sm2 + 128 * 32;

    const int mp   = blockIdx.x;
    const int tid  = threadIdx.x;
    const int w    = tid >> 5;
    const int lane = tid & 31;

    for (int half = 0; half < 2; half++) {
        const int m  = half ? (127 - mp) : mp;
        const int nl = NL - m;

        __syncthreads();   // previous half fully consumed before restaging
        for (int i = tid; i < 128 * 32; i += 256) {
            const int t = i >> 5, c = i & 31;
            float2 a = upk(g_F[t][m][c]);
            float2 b = upk(g_F[255 - t][m][c]);
            Fp[i] = pk2(a.x + b.x, a.y + b.y);
            Fm[i] = pk2(a.x - b.x, a.y - b.y);
        }
        __syncthreads();

        for (int li = w * 4; li < nl; li += 32) {
            u64 acc[4] = {0ull, 0ull, 0ull, 0ull};
            const int lmax = min(4, nl - li);
            const float* bp[4];
#pragma unroll
            for (int k = 0; k < 4; k++) {
                int l = m + li + k; if (l > 127) l = 127;
                bp[k] = leg + ((size_t)l * 255 + (127 + m)) * NT;
            }
#pragma unroll 4
            for (int t = 0; t < 128; t++) {
                u64 fp = Fp[t * 32 + lane];
                u64 fm = Fm[t * 32 + lane];
#pragma unroll
                for (int k = 0; k < 4; k++) {
                    float b = __ldg(bp[k] + t);
                    acc[k] = fma2(pk2(b, b), (k & 1) ? fm : fp, acc[k]);
                }
            }
            for (int k = 0; k < lmax; k++)
                g_flm[m][m + li + k][lane] = acc[k];
        }
    }
}

// ============================================================
// K3: channel mix, +m/-m weight pairs fused (DRAM-bound stream).
// ============================================================
__global__ __launch_bounds__(256) void k3_mix(const float* __restrict__ Wr,
                                              const float* __restrict__ Wi) {
    const int l = blockIdx.x;
    const int m = blockIdx.y;
    if (l < m) return;

    __shared__ float2 sf[32];
    __shared__ float2 red[8][32];
    const int tid = threadIdx.x, w = tid >> 5, lane = tid & 31;

    if (tid < 32) sf[tid] = ((const float2*)&g_flm[m][l][0])[tid];
    __syncthreads();

    const size_t bp = ((size_t)l * 255 + (127 + m)) * 1024;
    const size_t bn = ((size_t)l * 255 + (127 - m)) * 1024;

    float U = 0.0f, V = 0.0f;
#pragma unroll
    for (int k = 0; k < 4; k++) {
        const int c = w * 4 + k;
        const size_t op = bp + (size_t)c * 32 + lane;
        float wr = __ldcs(Wr + op);
        float wi = __ldcs(Wi + op);
        float S, D;
        if (m) {
            const size_t on = bn + (size_t)c * 32 + lane;
            S = wr + __ldcs(Wr + on);
            D = __ldcs(Wi + on) - wi;
        } else {
            S = wr; D = -wi;
        }
        const float fr = sf[c].x, fi = sf[c].y;
        U += fr * S; U += fi * D;
        V += fr * D; V -= fi * S;
    }
    red[w][lane] = make_float2(U, V);
    __syncthreads();
    if (w == 0) {
        float2 a = red[0][lane];
#pragma unroll
        for (int k = 1; k < 8; k++) { a.x += red[k][lane].x; a.y += red[k][lane].y; }
        g_uv[m][l][lane] = pk2(a.x, a.y);
    }
}

// ============================================================
// K4: Legendre synthesis, theta-parity folded, m-pair balanced.
// block (mp, tg): handles m=mp and m=127-mp; t in [tg*32, tg*32+32).
// grid (64, 4), block 256 (8 warps x 4 t, lane=o).
// dynamic smem ~66KB: suv[132][32] u64, sPd[132][32] u64 (padded to mult-4 l).
// ============================================================
#define NLPAD 132
__global__ __launch_bounds__(256) void k4_synth(const float* __restrict__ leg) {
    extern __shared__ u64 sm4[];
    u64* suv = sm4;                // [132][32]
    u64* sPd = sm4 + NLPAD * 32;   // [132][32]

    const int mp  = blockIdx.x;
    const int tg  = blockIdx.y;
    const int tid = threadIdx.x, w = tid >> 5, lane = tid & 31;
    const int tb  = w * 4;

    for (int half = 0; half < 2; half++) {
        const int m   = half ? (127 - mp) : mp;
        const int nl  = NL - m;
        const int nlp = (nl + 3) & ~3;   // zero-padded to multiple of 4

        __syncthreads();   // previous half fully consumed before restaging
        for (int i = tid; i < nlp * 32; i += 256)
            suv[i] = (i < nl * 32) ? ((const u64*)&g_uv[m][m][0])[i] : 0ull;
        for (int i = tid; i < nlp * 32; i += 256) {
            const int il = i >> 5, tt = i & 31;
            float v = (il < nl) ? leg[((size_t)(m + il) * 255 + (127 + m)) * NT + tg * 32 + tt] : 0.0f;
            sPd[i] = pk2(v, v);
        }
        __syncthreads();

        u64 E[4] = {0ull, 0ull, 0ull, 0ull};
        u64 O[4] = {0ull, 0ull, 0ull, 0ull};

#pragma unroll 2
        for (int il = 0; il < nlp; il += 2) {
            const u64 uv0 = suv[il * 32 + lane];
            const u64 uv1 = suv[(il + 1) * 32 + lane];
            const ulonglong2* p0 = (const ulonglong2*)(sPd + il * 32 + tb);
            const ulonglong2* p1 = (const ulonglong2*)(sPd + (il + 1) * 32 + tb);
            ulonglong2 pa = p0[0], pb = p0[1];
            ulonglong2 pc = p1[0], pd = p1[1];
            E[0] = fma2(pa.x, uv0, E[0]);
            E[1] = fma2(pa.y, uv0, E[1]);
            E[2] = fma2(pb.x, uv0, E[2]);
            E[3] = fma2(pb.y, uv0, E[3]);
            O[0] = fma2(pc.x, uv1, O[0]);
            O[1] = fma2(pc.y, uv1, O[1]);
            O[2] = fma2(pd.x, uv1, O[2]);
            O[3] = fma2(pd.y, uv1, O[3]);
        }

#pragma unroll
        for (int j = 0; j < 4; j++) {
            const int t = tg * 32 + tb + j;
            float2 e = upk(E[j]), o2 = upk(O[j]);
            g_AB[t][m][lane]       = pk2(e.x + o2.x, e.y + o2.y);
            g_AB[255 - t][m][lane] = pk2(e.x - o2.x, e.y - o2.y);
        }
    }
}

// ============================================================
// K5: inverse transform, even/odd-m folded: p<256 produces p and p+256.
// grid 256 (t), block 512 = 256 p x 2 o-groups (16 o each).
// ============================================================
__global__ __launch_bounds__(512, 1) void k5_idft(float* __restrict__ out) {
    __shared__ u64 sAB[128 * 32];
    const int t   = blockIdx.x;
    const int tid = threadIdx.x;
    const int p   = tid & 255;
    const int ob  = (tid >> 8) * 16;

    for (int i = tid; i < 128 * 32; i += 512)
        sAB[i] = ((const u64*)&g_AB[t][0][0])[i];
    __syncthreads();

    u64 E[16], O[16];
#pragma unroll
    for (int k = 0; k < 16; k++) { E[k] = 0ull; O[k] = 0ull; }

    float sd, cd;
    sincosf(((float)M_PI / 256.0f) * (float)p, &sd, &cd);
    u64 CDD = pk2(cd, cd);
    u64 P1 = pk2(-sd, sd), P2 = pk2(sd, -sd);
    u64 cs = pk2(1.0f, 0.0f), sc = pk2(0.0f, 1.0f);

#pragma unroll 2
    for (int m = 0; m < 128; m += 2) {
        const ulonglong2* r0 = (const ulonglong2*)(sAB + m * 32 + ob);
#pragma unroll
        for (int k = 0; k < 8; k++) {
            ulonglong2 v = r0[k];
            E[2 * k]     = fma2(v.x, cs, E[2 * k]);
            E[2 * k + 1] = fma2(v.y, cs, E[2 * k + 1]);
        }
        { u64 t1 = mul2(sc, P1); u64 nc = fma2(cs, CDD, t1);
          u64 t2 = mul2(cs, P2); sc = fma2(sc, CDD, t2); cs = nc; }

        const ulonglong2* r1 = (const ulonglong2*)(sAB + (m + 1) * 32 + ob);
#pragma unroll
        for (int k = 0; k < 8; k++) {
            ulonglong2 v = r1[k];
            O[2 * k]     = fma2(v.x, cs, O[2 * k]);
            O[2 * k + 1] = fma2(v.y, cs, O[2 * k + 1]);
        }
        { u64 t1 = mul2(sc, P1); u64 nc = fma2(cs, CDD, t1);
          u64 t2 = mul2(cs, P2); sc = fma2(sc, CDD, t2); cs = nc; }
    }

#pragma unroll
    for (int k = 0; k < 16; k++) {
        float2 e = upk(E[k]), o2 = upk(O[k]);
        const float ev = e.x + e.y, ov = o2.x + o2.y;
        const size_t base = ((size_t)(ob + k) * NT + t) * NP;
        out[base + p]       = ev + ov;
        out[base + p + 256] = ev - ov;
    }
}

// ============================================================
extern "C" void kernel_launch(void* const* d_in, const int* in_sizes, int n_in,
                              void* d_out, int out_size) {
    const float* x   = (const float*)d_in[0];
    const float* Wr  = (const float*)d_in[1];
    const float* Wi  = (const float*)d_in[2];
    const float* leg = (const float*)d_in[3];
    const float* wq  = (const float*)d_in[4];
    float* out = (float*)d_out;

    cudaFuncSetAttribute(k1_dft,      cudaFuncAttributeMaxDynamicSharedMemorySize, 65536);
    cudaFuncSetAttribute(k2_analysis, cudaFuncAttributeMaxDynamicSharedMemorySize, 65536);
    cudaFuncSetAttribute(k4_synth,    cudaFuncAttributeMaxDynamicSharedMemorySize, NLPAD * 32 * 8 * 2);

    k1_dft<<<256, 128, 65536>>>(x, wq);
    k2_analysis<<<64, 256, 65536>>>(leg);
    k3_mix<<<dim3(128, 128), 256>>>(Wr, Wi);
    k4_synth<<<dim3(64, 4), 256, NLPAD * 32 * 8 * 2>>>(leg);
    k5_idft<<<256, 512>>>(out);
}

// round 5
// speedup vs baseline: 1.7939x; 1.0165x over previous
#include <cuda_runtime.h>
#include <math.h>

#define NT 256   // ntheta
#define NP 512   // nphi
#define NC 32    // channels
#define NL 128   // L

typedef unsigned long long u64;

// ---------- packed f32x2 helpers (sm_103a FFMA2) ----------
__device__ __forceinline__ u64 pk2(float a, float b) {
    u64 r; asm("mov.b64 %0,{%1,%2};" : "=l"(r) : "f"(a), "f"(b)); return r;
}
__device__ __forceinline__ float2 upk(u64 v) {
    float2 f; asm("mov.b64 {%0,%1},%2;" : "=f"(f.x), "=f"(f.y) : "l"(v)); return f;
}
__device__ __forceinline__ u64 fma2(u64 a, u64 b, u64 c) {
    u64 d; asm("fma.rn.f32x2 %0,%1,%2,%3;" : "=l"(d) : "l"(a), "l"(b), "l"(c)); return d;
}
__device__ __forceinline__ u64 mul2(u64 a, u64 b) {
    u64 d; asm("mul.rn.f32x2 %0,%1,%2;" : "=l"(d) : "l"(a), "l"(b)); return d;
}

// ---------- static device scratch ----------
__device__ u64 g_F  [NT][NL][NC];   // (re,im) of F[t][m][c], wq*2pi/512 folded in
__device__ u64 g_flm[NL][NL][NC];   // [m][l][c]; valid only l>=m
__device__ u64 g_uv [NL][NL][NC];   // [m][l][o]; valid only l>=m
__device__ u64 g_AB [NT][NL][NC];   // [t][m][o] (A,B)

// ============================================================
// K1: forward DFT over phi, radix-2 folded (q and q+256 share twiddles).
// grid 256 (t), block 128 (m). dynamic smem 64KB: ype/ymo[256][16] u64.
// ============================================================
__global__ __launch_bounds__(128) void k1_dft(const float* __restrict__ x,
                                              const float* __restrict__ wq) {
    extern __shared__ u64 sm1[];
    u64* ype = sm1;              // [256][16]
    u64* ymo = sm1 + 256 * 16;   // [256][16]

    const int t   = blockIdx.x;
    const int tid = threadIdx.x;
    const int w   = tid >> 5;
    const int lane = tid & 31;
    const int par = w >> 1;                       // 0: even m, 1: odd m
    const int m   = 2 * (((w & 1) << 5) + lane) + par;

    {
        const float s = wq[t] * (2.0f * (float)M_PI / 512.0f);
        const float4* x4 = (const float4*)(x + (size_t)t * NP * NC);
        for (int i = tid; i < 2048; i += 128) {
            float4 a = x4[i];
            float4 b = x4[i + 2048];
            const int p = i >> 3, j = i & 7;
            ype[p * 16 + j * 2]     = pk2((a.x + b.x) * s, (a.y + b.y) * s);
            ype[p * 16 + j * 2 + 1] = pk2((a.z + b.z) * s, (a.w + b.w) * s);
            ymo[p * 16 + j * 2]     = pk2((a.x - b.x) * s, (a.y - b.y) * s);
            ymo[p * 16 + j * 2 + 1] = pk2((a.z - b.z) * s, (a.w - b.w) * s);
        }
    }
    __syncthreads();

    const u64* yrow = par ? ymo : ype;

    float sd, cd;
    sincosf(-(float)M_PI / 256.0f * (float)m, &sd, &cd);
    u64 CDD = pk2(cd, cd), SDD = pk2(sd, sd), NSD = pk2(-sd, -sd);
    u64 CC = pk2(1.0f, 1.0f), SS = pk2(0.0f, 0.0f);

    u64 aR[16], aI[16];
#pragma unroll
    for (int k = 0; k < 16; k++) { aR[k] = 0ull; aI[k] = 0ull; }

#pragma unroll 4
    for (int q = 0; q < 256; q++) {
        const ulonglong2* row = (const ulonglong2*)(yrow + q * 16);
#pragma unroll
        for (int k = 0; k < 8; k++) {
            ulonglong2 v = row[k];
            aR[2 * k]     = fma2(v.x, CC, aR[2 * k]);
            aI[2 * k]     = fma2(v.x, SS, aI[2 * k]);
            aR[2 * k + 1] = fma2(v.y, CC, aR[2 * k + 1]);
            aI[2 * k + 1] = fma2(v.y, SS, aI[2 * k + 1]);
        }
        u64 t1 = mul2(SS, NSD);
        u64 nC = fma2(CC, CDD, t1);
        u64 t2 = mul2(CC, SDD);
        SS = fma2(SS, CDD, t2);
        CC = nC;
    }

    ulonglong2* fout = (ulonglong2*)&g_F[t][m][0];
#pragma unroll
    for (int k = 0; k < 16; k++) {
        float2 r = upk(aR[k]), i2 = upk(aI[k]);
        fout[k] = make_ulonglong2(pk2(r.x, i2.x), pk2(r.y, i2.y));
    }
}

// ============================================================
// K2: Legendre analysis, theta-parity folded (t<128), m-pair balanced,
// l-range split over blockIdx.y (2) for occupancy.
// grid (64,2), block 256. dynamic smem 64KB: Fp/Fm[128][32] u64.
// ============================================================
__global__ __launch_bounds__(256) void k2_analysis(const float* __restrict__ leg) {
    extern __shared__ u64 sm2[];
    u64* Fp = sm2;               // [128][32]
    u64* Fm = sm2 + 128 * 32;

    const int mp   = blockIdx.x;
    const int lh   = blockIdx.y;
    const int tid  = threadIdx.x;
    const int w    = tid >> 5;
    const int lane = tid & 31;

    for (int half = 0; half < 2; half++) {
        const int m  = half ? (127 - mp) : mp;
        const int nl = NL - m;

        __syncthreads();
        for (int i = tid; i < 128 * 32; i += 256) {
            const int t = i >> 5, c = i & 31;
            float2 a = upk(g_F[t][m][c]);
            float2 b = upk(g_F[255 - t][m][c]);
            Fp[i] = pk2(a.x + b.x, a.y + b.y);
            Fm[i] = pk2(a.x - b.x, a.y - b.y);
        }
        __syncthreads();

        for (int li = (lh * 8 + w) * 4; li < nl; li += 64) {
            u64 acc[4] = {0ull, 0ull, 0ull, 0ull};
            const int lmax = min(4, nl - li);
            const float* bp[4];
#pragma unroll
            for (int k = 0; k < 4; k++) {
                int l = m + li + k; if (l > 127) l = 127;
                bp[k] = leg + ((size_t)l * 255 + (127 + m)) * NT;
            }
#pragma unroll 4
            for (int t = 0; t < 128; t++) {
                u64 fp = Fp[t * 32 + lane];
                u64 fm = Fm[t * 32 + lane];
#pragma unroll
                for (int k = 0; k < 4; k++) {
                    float b = __ldg(bp[k] + t);
                    acc[k] = fma2(pk2(b, b), (k & 1) ? fm : fp, acc[k]);
                }
            }
            for (int k = 0; k < lmax; k++)
                g_flm[m][m + li + k][lane] = acc[k];
        }
    }
}

// ============================================================
// K3: channel mix, +m/-m weight pairs fused (DRAM-bound stream).
// ============================================================
__global__ __launch_bounds__(256) void k3_mix(const float* __restrict__ Wr,
                                              const float* __restrict__ Wi) {
    const int l = blockIdx.x;
    const int m = blockIdx.y;
    if (l < m) return;

    __shared__ float2 sf[32];
    __shared__ float2 red[8][32];
    const int tid = threadIdx.x, w = tid >> 5, lane = tid & 31;

    if (tid < 32) sf[tid] = ((const float2*)&g_flm[m][l][0])[tid];
    __syncthreads();

    const size_t bp = ((size_t)l * 255 + (127 + m)) * 1024;
    const size_t bn = ((size_t)l * 255 + (127 - m)) * 1024;

    float U = 0.0f, V = 0.0f;
#pragma unroll
    for (int k = 0; k < 4; k++) {
        const int c = w * 4 + k;
        const size_t op = bp + (size_t)c * 32 + lane;
        float wr = __ldcs(Wr + op);
        float wi = __ldcs(Wi + op);
        float S, D;
        if (m) {
            const size_t on = bn + (size_t)c * 32 + lane;
            S = wr + __ldcs(Wr + on);
            D = __ldcs(Wi + on) - wi;
        } else {
            S = wr; D = -wi;
        }
        const float fr = sf[c].x, fi = sf[c].y;
        U += fr * S; U += fi * D;
        V += fr * D; V -= fi * S;
    }
    red[w][lane] = make_float2(U, V);
    __syncthreads();
    if (w == 0) {
        float2 a = red[0][lane];
#pragma unroll
        for (int k = 1; k < 8; k++) { a.x += red[k][lane].x; a.y += red[k][lane].y; }
        g_uv[m][l][lane] = pk2(a.x, a.y);
    }
}

// ============================================================
// K4: Legendre synthesis, LDG-direct (no smem, no barriers).
// Theta-parity folded (t<128 -> t and 255-t), m-pair balanced.
// grid (64 mp, 8 tg), block 128 = 4 warps x 4 t, lane = o.
// Per il: 1 coalesced LDG.64 (uv) + 1 uniform LDG.128 (4 P scalars).
// ============================================================
__global__ __launch_bounds__(128) void k4_synth(const float* __restrict__ leg) {
    const int mp  = blockIdx.x;
    const int tg  = blockIdx.y;
    const int tid = threadIdx.x, w = tid >> 5, lane = tid & 31;
    const int t0  = tg * 16 + w * 4;   // first of this warp's 4 thetas

    for (int half = 0; half < 2; half++) {
        const int m  = half ? (127 - mp) : mp;
        const int nl = NL - m;

        const u64*   uvp = &g_uv[m][m][0];                              // [il][32]
        const float* Pp  = leg + ((size_t)m * 255 + (127 + m)) * NT + t0;  // stride 255*NT per il

        u64 E[4] = {0ull, 0ull, 0ull, 0ull};
        u64 O[4] = {0ull, 0ull, 0ull, 0ull};

        const int nle = nl & ~1;
#pragma unroll 4
        for (int il = 0; il < nle; il += 2) {
            const u64 uv0 = __ldg(uvp + il * 32 + lane);
            const u64 uv1 = __ldg(uvp + (il + 1) * 32 + lane);
            const float4 P0 = *(const float4*)(Pp + (size_t)il * (255 * NT));
            const float4 P1 = *(const float4*)(Pp + (size_t)(il + 1) * (255 * NT));
            E[0] = fma2(pk2(P0.x, P0.x), uv0, E[0]);
            E[1] = fma2(pk2(P0.y, P0.y), uv0, E[1]);
            E[2] = fma2(pk2(P0.z, P0.z), uv0, E[2]);
            E[3] = fma2(pk2(P0.w, P0.w), uv0, E[3]);
            O[0] = fma2(pk2(P1.x, P1.x), uv1, O[0]);
            O[1] = fma2(pk2(P1.y, P1.y), uv1, O[1]);
            O[2] = fma2(pk2(P1.z, P1.z), uv1, O[2]);
            O[3] = fma2(pk2(P1.w, P1.w), uv1, O[3]);
        }
        if (nl & 1) {           // last il is even -> E
            const int il = nl - 1;
            const u64 uv0 = __ldg(uvp + il * 32 + lane);
            const float4 P0 = *(const float4*)(Pp + (size_t)il * (255 * NT));
            E[0] = fma2(pk2(P0.x, P0.x), uv0, E[0]);
            E[1] = fma2(pk2(P0.y, P0.y), uv0, E[1]);
            E[2] = fma2(pk2(P0.z, P0.z), uv0, E[2]);
            E[3] = fma2(pk2(P0.w, P0.w), uv0, E[3]);
        }

#pragma unroll
        for (int j = 0; j < 4; j++) {
            const int t = t0 + j;
            float2 e = upk(E[j]), o2 = upk(O[j]);
            g_AB[t][m][lane]       = pk2(e.x + o2.x, e.y + o2.y);
            g_AB[255 - t][m][lane] = pk2(e.x - o2.x, e.y - o2.y);
        }
    }
}

// ============================================================
// K5: inverse transform, even/odd-m folded: p<256 produces p and p+256.
// grid 256 (t), block 512 = 256 p x 2 o-groups (16 o each).
// ============================================================
__global__ __launch_bounds__(512, 1) void k5_idft(float* __restrict__ out) {
    __shared__ u64 sAB[128 * 32];
    const int t   = blockIdx.x;
    const int tid = threadIdx.x;
    const int p   = tid & 255;
    const int ob  = (tid >> 8) * 16;

    for (int i = tid; i < 128 * 32; i += 512)
        sAB[i] = ((const u64*)&g_AB[t][0][0])[i];
    __syncthreads();

    u64 E[16], O[16];
#pragma unroll
    for (int k = 0; k < 16; k++) { E[k] = 0ull; O[k] = 0ull; }

    float sd, cd;
    sincosf(((float)M_PI / 256.0f) * (float)p, &sd, &cd);
    u64 CDD = pk2(cd, cd);
    u64 P1 = pk2(-sd, sd), P2 = pk2(sd, -sd);
    u64 cs = pk2(1.0f, 0.0f), sc = pk2(0.0f, 1.0f);

#pragma unroll 2
    for (int m = 0; m < 128; m += 2) {
        const ulonglong2* r0 = (const ulonglong2*)(sAB + m * 32 + ob);
#pragma unroll
        for (int k = 0; k < 8; k++) {
            ulonglong2 v = r0[k];
            E[2 * k]     = fma2(v.x, cs, E[2 * k]);
            E[2 * k + 1] = fma2(v.y, cs, E[2 * k + 1]);
        }
        { u64 t1 = mul2(sc, P1); u64 nc = fma2(cs, CDD, t1);
          u64 t2 = mul2(cs, P2); sc = fma2(sc, CDD, t2); cs = nc; }

        const ulonglong2* r1 = (const ulonglong2*)(sAB + (m + 1) * 32 + ob);
#pragma unroll
        for (int k = 0; k < 8; k++) {
            ulonglong2 v = r1[k];
            O[2 * k]     = fma2(v.x, cs, O[2 * k]);
            O[2 * k + 1] = fma2(v.y, cs, O[2 * k + 1]);
        }
        { u64 t1 = mul2(sc, P1); u64 nc = fma2(cs, CDD, t1);
          u64 t2 = mul2(cs, P2); sc = fma2(sc, CDD, t2); cs = nc; }
    }

#pragma unroll
    for (int k = 0; k < 16; k++) {
        float2 e = upk(E[k]), o2 = upk(O[k]);
        const float ev = e.x + e.y, ov = o2.x + o2.y;
        const size_t base = ((size_t)(ob + k) * NT + t) * NP;
        out[base + p]       = ev + ov;
        out[base + p + 256] = ev - ov;
    }
}

// ============================================================
extern "C" void kernel_launch(void* const* d_in, const int* in_sizes, int n_in,
                              void* d_out, int out_size) {
    const float* x   = (const float*)d_in[0];
    const float* Wr  = (const float*)d_in[1];
    const float* Wi  = (const float*)d_in[2];
    const float* leg = (const float*)d_in[3];
    const float* wq  = (const float*)d_in[4];
    float* out = (float*)d_out;

    cudaFuncSetAttribute(k1_dft,      cudaFuncAttributeMaxDynamicSharedMemorySize, 65536);
    cudaFuncSetAttribute(k2_analysis, cudaFuncAttributeMaxDynamicSharedMemorySize, 65536);

    k1_dft<<<256, 128, 65536>>>(x, wq);
    k2_analysis<<<dim3(64, 2), 256, 65536>>>(leg);
    k3_mix<<<dim3(128, 128), 256>>>(Wr, Wi);
    k4_synth<<<dim3(64, 8), 128>>>(leg);
    k5_idft<<<256, 512>>>(out);
}

// round 6
// speedup vs baseline: 1.8885x; 1.0527x over previous
#include <cuda_runtime.h>
#include <math.h>

#define NT 256   // ntheta
#define NP 512   // nphi
#define NC 32    // channels
#define NL 128   // L

typedef unsigned long long u64;

// ---------- packed f32x2 helpers (sm_103a FFMA2) ----------
__device__ __forceinline__ u64 pk2(float a, float b) {
    u64 r; asm("mov.b64 %0,{%1,%2};" : "=l"(r) : "f"(a), "f"(b)); return r;
}
__device__ __forceinline__ float2 upk(u64 v) {
    float2 f; asm("mov.b64 {%0,%1},%2;" : "=f"(f.x), "=f"(f.y) : "l"(v)); return f;
}
__device__ __forceinline__ u64 fma2(u64 a, u64 b, u64 c) {
    u64 d; asm("fma.rn.f32x2 %0,%1,%2,%3;" : "=l"(d) : "l"(a), "l"(b), "l"(c)); return d;
}
__device__ __forceinline__ u64 mul2(u64 a, u64 b) {
    u64 d; asm("mul.rn.f32x2 %0,%1,%2;" : "=l"(d) : "l"(a), "l"(b)); return d;
}

// ---------- static device scratch ----------
__device__ u64 g_F  [NT][NL][NC];   // (re,im) of F[t][m][c], wq*2pi/512 folded in
__device__ u64 g_flm[NL][NL][NC];   // [m][l][c]; valid only l>=m
__device__ u64 g_uv [NL][NL][NC];   // [m][l][o]; valid only l>=m
__device__ u64 g_AB [NT][NL][NC];   // [t][m][o] (A,B)

// ============================================================
// K1: forward DFT over phi, radix-2 folded (q and q+256 share twiddles).
// grid 256 (t), block 128 (m). dynamic smem 64KB: ype/ymo[256][16] u64.
// ============================================================
__global__ __launch_bounds__(128) void k1_dft(const float* __restrict__ x,
                                              const float* __restrict__ wq) {
    extern __shared__ u64 sm1[];
    u64* ype = sm1;              // [256][16]
    u64* ymo = sm1 + 256 * 16;   // [256][16]

    const int t   = blockIdx.x;
    const int tid = threadIdx.x;
    const int w   = tid >> 5;
    const int lane = tid & 31;
    const int par = w >> 1;                       // 0: even m, 1: odd m
    const int m   = 2 * (((w & 1) << 5) + lane) + par;

    {
        const float s = wq[t] * (2.0f * (float)M_PI / 512.0f);
        const float4* x4 = (const float4*)(x + (size_t)t * NP * NC);
        for (int i = tid; i < 2048; i += 128) {
            float4 a = x4[i];
            float4 b = x4[i + 2048];
            const int p = i >> 3, j = i & 7;
            ype[p * 16 + j * 2]     = pk2((a.x + b.x) * s, (a.y + b.y) * s);
            ype[p * 16 + j * 2 + 1] = pk2((a.z + b.z) * s, (a.w + b.w) * s);
            ymo[p * 16 + j * 2]     = pk2((a.x - b.x) * s, (a.y - b.y) * s);
            ymo[p * 16 + j * 2 + 1] = pk2((a.z - b.z) * s, (a.w - b.w) * s);
        }
    }
    __syncthreads();

    const u64* yrow = par ? ymo : ype;

    float sd, cd;
    sincosf(-(float)M_PI / 256.0f * (float)m, &sd, &cd);
    u64 CDD = pk2(cd, cd), SDD = pk2(sd, sd), NSD = pk2(-sd, -sd);
    u64 CC = pk2(1.0f, 1.0f), SS = pk2(0.0f, 0.0f);

    u64 aR[16], aI[16];
#pragma unroll
    for (int k = 0; k < 16; k++) { aR[k] = 0ull; aI[k] = 0ull; }

#pragma unroll 4
    for (int q = 0; q < 256; q++) {
        const ulonglong2* row = (const ulonglong2*)(yrow + q * 16);
#pragma unroll
        for (int k = 0; k < 8; k++) {
            ulonglong2 v = row[k];
            aR[2 * k]     = fma2(v.x, CC, aR[2 * k]);
            aI[2 * k]     = fma2(v.x, SS, aI[2 * k]);
            aR[2 * k + 1] = fma2(v.y, CC, aR[2 * k + 1]);
            aI[2 * k + 1] = fma2(v.y, SS, aI[2 * k + 1]);
        }
        u64 t1 = mul2(SS, NSD);
        u64 nC = fma2(CC, CDD, t1);
        u64 t2 = mul2(CC, SDD);
        SS = fma2(SS, CDD, t2);
        CC = nC;
    }

    ulonglong2* fout = (ulonglong2*)&g_F[t][m][0];
#pragma unroll
    for (int k = 0; k < 16; k++) {
        float2 r = upk(aR[k]), i2 = upk(aI[k]);
        fout[k] = make_ulonglong2(pk2(r.x, i2.x), pk2(r.y, i2.y));
    }
}

// ============================================================
// K2: Legendre analysis, theta-parity folded (t<128), m-pair balanced,
// l-range split over blockIdx.y (2) for occupancy.
// grid (64,2), block 256. dynamic smem 64KB: Fp/Fm[128][32] u64.
// ============================================================
__global__ __launch_bounds__(256) void k2_analysis(const float* __restrict__ leg) {
    extern __shared__ u64 sm2[];
    u64* Fp = sm2;               // [128][32]
    u64* Fm = sm2 + 128 * 32;

    const int mp   = blockIdx.x;
    const int lh   = blockIdx.y;
    const int tid  = threadIdx.x;
    const int w    = tid >> 5;
    const int lane = tid & 31;

    for (int half = 0; half < 2; half++) {
        const int m  = half ? (127 - mp) : mp;
        const int nl = NL - m;

        __syncthreads();
        for (int i = tid; i < 128 * 32; i += 256) {
            const int t = i >> 5, c = i & 31;
            float2 a = upk(g_F[t][m][c]);
            float2 b = upk(g_F[255 - t][m][c]);
            Fp[i] = pk2(a.x + b.x, a.y + b.y);
            Fm[i] = pk2(a.x - b.x, a.y - b.y);
        }
        __syncthreads();

        for (int li = (lh * 8 + w) * 4; li < nl; li += 64) {
            u64 acc[4] = {0ull, 0ull, 0ull, 0ull};
            const int lmax = min(4, nl - li);
            const float* bp[4];
#pragma unroll
            for (int k = 0; k < 4; k++) {
                int l = m + li + k; if (l > 127) l = 127;
                bp[k] = leg + ((size_t)l * 255 + (127 + m)) * NT;
            }
#pragma unroll 4
            for (int t = 0; t < 128; t++) {
                u64 fp = Fp[t * 32 + lane];
                u64 fm = Fm[t * 32 + lane];
#pragma unroll
                for (int k = 0; k < 4; k++) {
                    float b = __ldg(bp[k] + t);
                    acc[k] = fma2(pk2(b, b), (k & 1) ? fm : fp, acc[k]);
                }
            }
            for (int k = 0; k < lmax; k++)
                g_flm[m][m + li + k][lane] = acc[k];
        }
    }
}

// ============================================================
// K3: channel mix, +m/-m weight pairs fused (DRAM-bound stream).
// ============================================================
__global__ __launch_bounds__(256) void k3_mix(const float* __restrict__ Wr,
                                              const float* __restrict__ Wi) {
    const int l = blockIdx.x;
    const int m = blockIdx.y;
    if (l < m) return;

    __shared__ float2 sf[32];
    __shared__ float2 red[8][32];
    const int tid = threadIdx.x, w = tid >> 5, lane = tid & 31;

    if (tid < 32) sf[tid] = ((const float2*)&g_flm[m][l][0])[tid];
    __syncthreads();

    const size_t bp = ((size_t)l * 255 + (127 + m)) * 1024;
    const size_t bn = ((size_t)l * 255 + (127 - m)) * 1024;

    float U = 0.0f, V = 0.0f;
#pragma unroll
    for (int k = 0; k < 4; k++) {
        const int c = w * 4 + k;
        const size_t op = bp + (size_t)c * 32 + lane;
        float wr = __ldcs(Wr + op);
        float wi = __ldcs(Wi + op);
        float S, D;
        if (m) {
            const size_t on = bn + (size_t)c * 32 + lane;
            S = wr + __ldcs(Wr + on);
            D = __ldcs(Wi + on) - wi;
        } else {
            S = wr; D = -wi;
        }
        const float fr = sf[c].x, fi = sf[c].y;
        U += fr * S; U += fi * D;
        V += fr * D; V -= fi * S;
    }
    red[w][lane] = make_float2(U, V);
    __syncthreads();
    if (w == 0) {
        float2 a = red[0][lane];
#pragma unroll
        for (int k = 1; k < 8; k++) { a.x += red[k][lane].x; a.y += red[k][lane].y; }
        g_uv[m][l][lane] = pk2(a.x, a.y);
    }
}

// ============================================================
// K4: Legendre synthesis. uv staged once in smem (32KB, coalesced);
// P via uniform LDG.128 (warp-broadcast). Theta-parity folded.
// grid (128 m, 4 tg), block 256 = 8 warps x 4 t, lane = o.
// ============================================================
__global__ __launch_bounds__(256) void k4_synth(const float* __restrict__ leg) {
    __shared__ u64 suv[128 * 32];    // 32 KB

    const int m   = blockIdx.x;
    const int tg  = blockIdx.y;
    const int nl  = NL - m;
    const int tid = threadIdx.x, w = tid >> 5, lane = tid & 31;
    const int t0  = tg * 32 + w * 4;   // this warp's 4 thetas

    const u64* uvp = &g_uv[m][m][0];
    for (int i = tid; i < nl * 32; i += 256) suv[i] = uvp[i];
    __syncthreads();

    const float* Pp = leg + ((size_t)m * 255 + (127 + m)) * NT + t0;  // +255*NT per il

    u64 E[4] = {0ull, 0ull, 0ull, 0ull};
    u64 O[4] = {0ull, 0ull, 0ull, 0ull};

    const int nle = nl & ~1;
#pragma unroll 4
    for (int il = 0; il < nle; il += 2) {
        const u64 uv0 = suv[il * 32 + lane];
        const u64 uv1 = suv[(il + 1) * 32 + lane];
        const float4 P0 = *(const float4*)(Pp + (size_t)il * (255 * NT));
        const float4 P1 = *(const float4*)(Pp + (size_t)(il + 1) * (255 * NT));
        E[0] = fma2(pk2(P0.x, P0.x), uv0, E[0]);
        E[1] = fma2(pk2(P0.y, P0.y), uv0, E[1]);
        E[2] = fma2(pk2(P0.z, P0.z), uv0, E[2]);
        E[3] = fma2(pk2(P0.w, P0.w), uv0, E[3]);
        O[0] = fma2(pk2(P1.x, P1.x), uv1, O[0]);
        O[1] = fma2(pk2(P1.y, P1.y), uv1, O[1]);
        O[2] = fma2(pk2(P1.z, P1.z), uv1, O[2]);
        O[3] = fma2(pk2(P1.w, P1.w), uv1, O[3]);
    }
    if (nl & 1) {           // last il is even -> E
        const int il = nl - 1;
        const u64 uv0 = suv[il * 32 + lane];
        const float4 P0 = *(const float4*)(Pp + (size_t)il * (255 * NT));
        E[0] = fma2(pk2(P0.x, P0.x), uv0, E[0]);
        E[1] = fma2(pk2(P0.y, P0.y), uv0, E[1]);
        E[2] = fma2(pk2(P0.z, P0.z), uv0, E[2]);
        E[3] = fma2(pk2(P0.w, P0.w), uv0, E[3]);
    }

#pragma unroll
    for (int j = 0; j < 4; j++) {
        const int t = t0 + j;
        float2 e = upk(E[j]), o2 = upk(O[j]);
        g_AB[t][m][lane]       = pk2(e.x + o2.x, e.y + o2.y);
        g_AB[255 - t][m][lane] = pk2(e.x - o2.x, e.y - o2.y);
    }
}

// ============================================================
// K5: inverse transform, even/odd-m folded: p<256 produces p and p+256.
// grid (256 t, 2 og), block 256 (p). Stages only its 16-channel half (16KB).
// ============================================================
__global__ __launch_bounds__(256) void k5_idft(float* __restrict__ out) {
    __shared__ u64 sAB[128 * 16];    // 16 KB
    const int t  = blockIdx.x;
    const int ob = blockIdx.y * 16;
    const int p  = threadIdx.x;

    for (int i = p; i < 128 * 16; i += 256) {
        const int m = i >> 4, o = i & 15;
        sAB[i] = g_AB[t][m][ob + o];
    }
    __syncthreads();

    u64 E[16], O[16];
#pragma unroll
    for (int k = 0; k < 16; k++) { E[k] = 0ull; O[k] = 0ull; }

    float sd, cd;
    sincosf(((float)M_PI / 256.0f) * (float)p, &sd, &cd);
    u64 CDD = pk2(cd, cd);
    u64 P1 = pk2(-sd, sd), P2 = pk2(sd, -sd);
    u64 cs = pk2(1.0f, 0.0f), sc = pk2(0.0f, 1.0f);

#pragma unroll 2
    for (int m = 0; m < 128; m += 2) {
        const ulonglong2* r0 = (const ulonglong2*)(sAB + m * 16);
#pragma unroll
        for (int k = 0; k < 8; k++) {
            ulonglong2 v = r0[k];
            E[2 * k]     = fma2(v.x, cs, E[2 * k]);
            E[2 * k + 1] = fma2(v.y, cs, E[2 * k + 1]);
        }
        { u64 t1 = mul2(sc, P1); u64 nc = fma2(cs, CDD, t1);
          u64 t2 = mul2(cs, P2); sc = fma2(sc, CDD, t2); cs = nc; }

        const ulonglong2* r1 = (const ulonglong2*)(sAB + (m + 1) * 16);
#pragma unroll
        for (int k = 0; k < 8; k++) {
            ulonglong2 v = r1[k];
            O[2 * k]     = fma2(v.x, cs, O[2 * k]);
            O[2 * k + 1] = fma2(v.y, cs, O[2 * k + 1]);
        }
        { u64 t1 = mul2(sc, P1); u64 nc = fma2(cs, CDD, t1);
          u64 t2 = mul2(cs, P2); sc = fma2(sc, CDD, t2); cs = nc; }
    }

#pragma unroll
    for (int k = 0; k < 16; k++) {
        float2 e = upk(E[k]), o2 = upk(O[k]);
        const float ev = e.x + e.y, ov = o2.x + o2.y;
        const size_t base = ((size_t)(ob + k) * NT + t) * NP;
        out[base + p]       = ev + ov;
        out[base + p + 256] = ev - ov;
    }
}

// ============================================================
extern "C" void kernel_launch(void* const* d_in, const int* in_sizes, int n_in,
                              void* d_out, int out_size) {
    const float* x   = (const float*)d_in[0];
    const float* Wr  = (const float*)d_in[1];
    const float* Wi  = (const float*)d_in[2];
    const float* leg = (const float*)d_in[3];
    const float* wq  = (const float*)d_in[4];
    float* out = (float*)d_out;

    cudaFuncSetAttribute(k1_dft,      cudaFuncAttributeMaxDynamicSharedMemorySize, 65536);
    cudaFuncSetAttribute(k2_analysis, cudaFuncAttributeMaxDynamicSharedMemorySize, 65536);

    k1_dft<<<256, 128, 65536>>>(x, wq);
    k2_analysis<<<dim3(64, 2), 256, 65536>>>(leg);
    k3_mix<<<dim3(128, 128), 256>>>(Wr, Wi);
    k4_synth<<<dim3(128, 4), 256>>>(leg);
    k5_idft<<<dim3(256, 2), 256>>>(out);
}

// round 7
// speedup vs baseline: 1.9441x; 1.0295x over previous
#include <cuda_runtime.h>
#include <math.h>

#define NT 256   // ntheta
#define NP 512   // nphi
#define NC 32    // channels
#define NL 128   // L

typedef unsigned long long u64;

// ---------- packed f32x2 helpers (sm_103a FFMA2) ----------
__device__ __forceinline__ u64 pk2(float a, float b) {
    u64 r; asm("mov.b64 %0,{%1,%2};" : "=l"(r) : "f"(a), "f"(b)); return r;
}
__device__ __forceinline__ float2 upk(u64 v) {
    float2 f; asm("mov.b64 {%0,%1},%2;" : "=f"(f.x), "=f"(f.y) : "l"(v)); return f;
}
__device__ __forceinline__ u64 fma2(u64 a, u64 b, u64 c) {
    u64 d; asm("fma.rn.f32x2 %0,%1,%2,%3;" : "=l"(d) : "l"(a), "l"(b), "l"(c)); return d;
}
__device__ __forceinline__ u64 mul2(u64 a, u64 b) {
    u64 d; asm("mul.rn.f32x2 %0,%1,%2;" : "=l"(d) : "l"(a), "l"(b)); return d;
}

// ---------- static device scratch ----------
__device__ u64 g_F  [NT][NL][NC];   // (re,im) of F[t][m][c], wq*2pi/512 folded in
__device__ u64 g_flm[NL][NL][NC];   // [m][l][c]; valid only l>=m
__device__ u64 g_uv [NL][NL][NC];   // [m][l][o]; valid only l>=m
__device__ u64 g_AB [NT][NL][NC];   // [t][m][o] (A,B)

// ============================================================
// K1: forward DFT over phi, radix-2 folded (q and q+256 share twiddles).
// grid 256 (t), block 128 (m). dynamic smem 64KB: ype/ymo[256][16] u64.
// ============================================================
__global__ __launch_bounds__(128) void k1_dft(const float* __restrict__ x,
                                              const float* __restrict__ wq) {
    extern __shared__ u64 sm1[];
    u64* ype = sm1;              // [256][16]
    u64* ymo = sm1 + 256 * 16;   // [256][16]

    const int t   = blockIdx.x;
    const int tid = threadIdx.x;
    const int w   = tid >> 5;
    const int lane = tid & 31;
    const int par = w >> 1;                       // 0: even m, 1: odd m
    const int m   = 2 * (((w & 1) << 5) + lane) + par;

    {
        const float s = wq[t] * (2.0f * (float)M_PI / 512.0f);
        const float4* x4 = (const float4*)(x + (size_t)t * NP * NC);
        for (int i = tid; i < 2048; i += 128) {
            float4 a = x4[i];
            float4 b = x4[i + 2048];
            const int p = i >> 3, j = i & 7;
            ype[p * 16 + j * 2]     = pk2((a.x + b.x) * s, (a.y + b.y) * s);
            ype[p * 16 + j * 2 + 1] = pk2((a.z + b.z) * s, (a.w + b.w) * s);
            ymo[p * 16 + j * 2]     = pk2((a.x - b.x) * s, (a.y - b.y) * s);
            ymo[p * 16 + j * 2 + 1] = pk2((a.z - b.z) * s, (a.w - b.w) * s);
        }
    }
    __syncthreads();

    const u64* yrow = par ? ymo : ype;

    float sd, cd;
    sincosf(-(float)M_PI / 256.0f * (float)m, &sd, &cd);
    u64 CDD = pk2(cd, cd), SDD = pk2(sd, sd), NSD = pk2(-sd, -sd);
    u64 CC = pk2(1.0f, 1.0f), SS = pk2(0.0f, 0.0f);

    u64 aR[16], aI[16];
#pragma unroll
    for (int k = 0; k < 16; k++) { aR[k] = 0ull; aI[k] = 0ull; }

#pragma unroll 4
    for (int q = 0; q < 256; q++) {
        const ulonglong2* row = (const ulonglong2*)(yrow + q * 16);
#pragma unroll
        for (int k = 0; k < 8; k++) {
            ulonglong2 v = row[k];
            aR[2 * k]     = fma2(v.x, CC, aR[2 * k]);
            aI[2 * k]     = fma2(v.x, SS, aI[2 * k]);
            aR[2 * k + 1] = fma2(v.y, CC, aR[2 * k + 1]);
            aI[2 * k + 1] = fma2(v.y, SS, aI[2 * k + 1]);
        }
        u64 t1 = mul2(SS, NSD);
        u64 nC = fma2(CC, CDD, t1);
        u64 t2 = mul2(CC, SDD);
        SS = fma2(SS, CDD, t2);
        CC = nC;
    }

    ulonglong2* fout = (ulonglong2*)&g_F[t][m][0];
#pragma unroll
    for (int k = 0; k < 16; k++) {
        float2 r = upk(aR[k]), i2 = upk(aI[k]);
        fout[k] = make_ulonglong2(pk2(r.x, i2.x), pk2(r.y, i2.y));
    }
}

// ============================================================
// K2: Legendre analysis, theta-parity folded (t<128), m-pair balanced,
// l-range split over blockIdx.y (2) for occupancy.
// grid (64,2), block 256. dynamic smem 64KB: Fp/Fm[128][32] u64.
// ============================================================
__global__ __launch_bounds__(256) void k2_analysis(const float* __restrict__ leg) {
    extern __shared__ u64 sm2[];
    u64* Fp = sm2;               // [128][32]
    u64* Fm = sm2 + 128 * 32;

    const int mp   = blockIdx.x;
    const int lh   = blockIdx.y;
    const int tid  = threadIdx.x;
    const int w    = tid >> 5;
    const int lane = tid & 31;

    for (int half = 0; half < 2; half++) {
        const int m  = half ? (127 - mp) : mp;
        const int nl = NL - m;

        __syncthreads();
        for (int i = tid; i < 128 * 32; i += 256) {
            const int t = i >> 5, c = i & 31;
            float2 a = upk(g_F[t][m][c]);
            float2 b = upk(g_F[255 - t][m][c]);
            Fp[i] = pk2(a.x + b.x, a.y + b.y);
            Fm[i] = pk2(a.x - b.x, a.y - b.y);
        }
        __syncthreads();

        for (int li = (lh * 8 + w) * 4; li < nl; li += 64) {
            u64 acc[4] = {0ull, 0ull, 0ull, 0ull};
            const int lmax = min(4, nl - li);
            const float* bp[4];
#pragma unroll
            for (int k = 0; k < 4; k++) {
                int l = m + li + k; if (l > 127) l = 127;
                bp[k] = leg + ((size_t)l * 255 + (127 + m)) * NT;
            }
#pragma unroll 4
            for (int t = 0; t < 128; t++) {
                u64 fp = Fp[t * 32 + lane];
                u64 fm = Fm[t * 32 + lane];
#pragma unroll
                for (int k = 0; k < 4; k++) {
                    float b = __ldg(bp[k] + t);
                    acc[k] = fma2(pk2(b, b), (k & 1) ? fm : fp, acc[k]);
                }
            }
            for (int k = 0; k < lmax; k++)
                g_flm[m][m + li + k][lane] = acc[k];
        }
    }
}

// ============================================================
// K3: channel mix, +m/-m weight pairs fused (DRAM-bound stream).
// ============================================================
__global__ __launch_bounds__(256) void k3_mix(const float* __restrict__ Wr,
                                              const float* __restrict__ Wi) {
    const int l = blockIdx.x;
    const int m = blockIdx.y;
    if (l < m) return;

    __shared__ float2 sf[32];
    __shared__ float2 red[8][32];
    const int tid = threadIdx.x, w = tid >> 5, lane = tid & 31;

    if (tid < 32) sf[tid] = ((const float2*)&g_flm[m][l][0])[tid];
    __syncthreads();

    const size_t bp = ((size_t)l * 255 + (127 + m)) * 1024;
    const size_t bn = ((size_t)l * 255 + (127 - m)) * 1024;

    float U = 0.0f, V = 0.0f;
#pragma unroll
    for (int k = 0; k < 4; k++) {
        const int c = w * 4 + k;
        const size_t op = bp + (size_t)c * 32 + lane;
        float wr = __ldcs(Wr + op);
        float wi = __ldcs(Wi + op);
        float S, D;
        if (m) {
            const size_t on = bn + (size_t)c * 32 + lane;
            S = wr + __ldcs(Wr + on);
            D = __ldcs(Wi + on) - wi;
        } else {
            S = wr; D = -wi;
        }
        const float fr = sf[c].x, fi = sf[c].y;
        U += fr * S; U += fi * D;
        V += fr * D; V -= fi * S;
    }
    red[w][lane] = make_float2(U, V);
    __syncthreads();
    if (w == 0) {
        float2 a = red[0][lane];
#pragma unroll
        for (int k = 1; k < 8; k++) { a.x += red[k][lane].x; a.y += red[k][lane].y; }
        g_uv[m][l][lane] = pk2(a.x, a.y);
    }
}

// ============================================================
// K4: Legendre synthesis, all-smem inner loop (LDS only, no LDG in loop).
// uv AND P staged coalesced; P duplicated to u64 for LDS.128 pairs.
// Theta-parity folded (t<128 -> t and 255-t).
// grid (128 m, 4 tg), block 256 = 8 warps x 4 t, lane = o.
// dynamic smem 64KB: suv[128][32] u64 + sPd[128][32] u64.
// ============================================================
__global__ __launch_bounds__(256) void k4_synth(const float* __restrict__ leg) {
    extern __shared__ u64 sm4[];
    u64* suv = sm4;              // [128][32]
    u64* sPd = sm4 + 128 * 32;   // [128][32]

    const int m   = blockIdx.x;
    const int tg  = blockIdx.y;
    const int nl  = NL - m;
    const int nlp = (nl + 3) & ~3;   // zero-padded to multiple of 4
    const int tid = threadIdx.x, w = tid >> 5, lane = tid & 31;
    const int tb  = w * 4;

    const u64* uvp = &g_uv[m][m][0];
    for (int i = tid; i < nlp * 32; i += 256)
        suv[i] = (i < nl * 32) ? uvp[i] : 0ull;
    // coalesced P staging: per row il, 32 consecutive floats (one line)
    const float* Pp = leg + ((size_t)m * 255 + (127 + m)) * NT + tg * 32;
    for (int i = tid; i < nlp * 32; i += 256) {
        const int il = i >> 5, tt = i & 31;
        float v = (il < nl) ? __ldg(Pp + (size_t)il * (255 * NT) + tt) : 0.0f;
        sPd[i] = pk2(v, v);
    }
    __syncthreads();

    u64 E[4] = {0ull, 0ull, 0ull, 0ull};
    u64 O[4] = {0ull, 0ull, 0ull, 0ull};

#pragma unroll 2
    for (int il = 0; il < nlp; il += 2) {
        const u64 uv0 = suv[il * 32 + lane];
        const u64 uv1 = suv[(il + 1) * 32 + lane];
        const ulonglong2* p0 = (const ulonglong2*)(sPd + il * 32 + tb);
        const ulonglong2* p1 = (const ulonglong2*)(sPd + (il + 1) * 32 + tb);
        ulonglong2 pa = p0[0], pb = p0[1];
        ulonglong2 pc = p1[0], pd = p1[1];
        E[0] = fma2(pa.x, uv0, E[0]);
        E[1] = fma2(pa.y, uv0, E[1]);
        E[2] = fma2(pb.x, uv0, E[2]);
        E[3] = fma2(pb.y, uv0, E[3]);
        O[0] = fma2(pc.x, uv1, O[0]);
        O[1] = fma2(pc.y, uv1, O[1]);
        O[2] = fma2(pd.x, uv1, O[2]);
        O[3] = fma2(pd.y, uv1, O[3]);
    }

#pragma unroll
    for (int j = 0; j < 4; j++) {
        const int t = tg * 32 + tb + j;
        float2 e = upk(E[j]), o2 = upk(O[j]);
        g_AB[t][m][lane]       = pk2(e.x + o2.x, e.y + o2.y);
        g_AB[255 - t][m][lane] = pk2(e.x - o2.x, e.y - o2.y);
    }
}

// ============================================================
// K5: inverse transform, even/odd-m folded: p<256 produces p and p+256.
// grid (256 t, 2 og), block 256 (p). Stages only its 16-channel half (16KB).
// ============================================================
__global__ __launch_bounds__(256) void k5_idft(float* __restrict__ out) {
    __shared__ u64 sAB[128 * 16];    // 16 KB
    const int t  = blockIdx.x;
    const int ob = blockIdx.y * 16;
    const int p  = threadIdx.x;

    for (int i = p; i < 128 * 16; i += 256) {
        const int m = i >> 4, o = i & 15;
        sAB[i] = g_AB[t][m][ob + o];
    }
    __syncthreads();

    u64 E[16], O[16];
#pragma unroll
    for (int k = 0; k < 16; k++) { E[k] = 0ull; O[k] = 0ull; }

    float sd, cd;
    sincosf(((float)M_PI / 256.0f) * (float)p, &sd, &cd);
    u64 CDD = pk2(cd, cd);
    u64 P1 = pk2(-sd, sd), P2 = pk2(sd, -sd);
    u64 cs = pk2(1.0f, 0.0f), sc = pk2(0.0f, 1.0f);

#pragma unroll 2
    for (int m = 0; m < 128; m += 2) {
        const ulonglong2* r0 = (const ulonglong2*)(sAB + m * 16);
#pragma unroll
        for (int k = 0; k < 8; k++) {
            ulonglong2 v = r0[k];
            E[2 * k]     = fma2(v.x, cs, E[2 * k]);
            E[2 * k + 1] = fma2(v.y, cs, E[2 * k + 1]);
        }
        { u64 t1 = mul2(sc, P1); u64 nc = fma2(cs, CDD, t1);
          u64 t2 = mul2(cs, P2); sc = fma2(sc, CDD, t2); cs = nc; }

        const ulonglong2* r1 = (const ulonglong2*)(sAB + (m + 1) * 16);
#pragma unroll
        for (int k = 0; k < 8; k++) {
            ulonglong2 v = r1[k];
            O[2 * k]     = fma2(v.x, cs, O[2 * k]);
            O[2 * k + 1] = fma2(v.y, cs, O[2 * k + 1]);
        }
        { u64 t1 = mul2(sc, P1); u64 nc = fma2(cs, CDD, t1);
          u64 t2 = mul2(cs, P2); sc = fma2(sc, CDD, t2); cs = nc; }
    }

#pragma unroll
    for (int k = 0; k < 16; k++) {
        float2 e = upk(E[k]), o2 = upk(O[k]);
        const float ev = e.x + e.y, ov = o2.x + o2.y;
        const size_t base = ((size_t)(ob + k) * NT + t) * NP;
        out[base + p]       = ev + ov;
        out[base + p + 256] = ev - ov;
    }
}

// ============================================================
extern "C" void kernel_launch(void* const* d_in, const int* in_sizes, int n_in,
                              void* d_out, int out_size) {
    const float* x   = (const float*)d_in[0];
    const float* Wr  = (const float*)d_in[1];
    const float* Wi  = (const float*)d_in[2];
    const float* leg = (const float*)d_in[3];
    const float* wq  = (const float*)d_in[4];
    float* out = (float*)d_out;

    cudaFuncSetAttribute(k1_dft,      cudaFuncAttributeMaxDynamicSharedMemorySize, 65536);
    cudaFuncSetAttribute(k2_analysis, cudaFuncAttributeMaxDynamicSharedMemorySize, 65536);
    cudaFuncSetAttribute(k4_synth,    cudaFuncAttributeMaxDynamicSharedMemorySize, 65536);

    k1_dft<<<256, 128, 65536>>>(x, wq);
    k2_analysis<<<dim3(64, 2), 256, 65536>>>(leg);
    k3_mix<<<dim3(128, 128), 256>>>(Wr, Wi);
    k4_synth<<<dim3(128, 4), 256, 65536>>>(leg);
    k5_idft<<<dim3(256, 2), 256>>>(out);
}

// round 8
// speedup vs baseline: 2.1729x; 1.1177x over previous
#include <cuda_runtime.h>
#include <math.h>

#define NT 256   // ntheta
#define NP 512   // nphi
#define NC 32    // channels
#define NL 128   // L

typedef unsigned long long u64;

// ---------- packed f32x2 helpers (sm_103a FFMA2) ----------
__device__ __forceinline__ u64 pk2(float a, float b) {
    u64 r; asm("mov.b64 %0,{%1,%2};" : "=l"(r) : "f"(a), "f"(b)); return r;
}
__device__ __forceinline__ float2 upk(u64 v) {
    float2 f; asm("mov.b64 {%0,%1},%2;" : "=f"(f.x), "=f"(f.y) : "l"(v)); return f;
}
__device__ __forceinline__ u64 fma2(u64 a, u64 b, u64 c) {
    u64 d; asm("fma.rn.f32x2 %0,%1,%2,%3;" : "=l"(d) : "l"(a), "l"(b), "l"(c)); return d;
}
__device__ __forceinline__ u64 mul2(u64 a, u64 b) {
    u64 d; asm("mul.rn.f32x2 %0,%1,%2;" : "=l"(d) : "l"(a), "l"(b)); return d;
}

// ---------- static device scratch ----------
__device__ u64 g_F  [NT][NL][NC];   // (re,im) of F[t][m][c], wq*2pi/512 folded in
__device__ u64 g_flm[NL][NL][NC];   // [m][l][c]; valid only l>=m
__device__ u64 g_uv [NL][NL][NC];   // [m][l][o]; valid only l>=m
__device__ u64 g_AB [NT][NL][NC];   // [t][m][o] (A,B)

// ============================================================
// K1: forward DFT over phi, radix-2 folded + q-reflection folded.
// After parity fold, y_q (q in [0,256)). Reflection q<->256-q:
//   even m: R uses (y_q + y_{256-q}) = slot q;  I uses (y_q - y_{256-q}) = slot 256-q
//   odd  m: roles swap.
// Edges: q=0 -> R += y0; q=128 -> R += (-1)^{m/2} y128 (even m),
//        I += -(-1)^{(m-1)/2} y128 (odd m).
// grid 256 (t), block 128 (m). dynamic smem 64KB.
// ============================================================
__global__ __launch_bounds__(128) void k1_dft(const float* __restrict__ x,
                                              const float* __restrict__ wq) {
    extern __shared__ u64 sm1[];
    u64* ype = sm1;              // [256][16]
    u64* ymo = sm1 + 4096;       // [256][16]

    const int t   = blockIdx.x;
    const int tid = threadIdx.x;
    const int w   = tid >> 5;
    const int lane = tid & 31;
    const int par = w >> 1;                       // 0: even m, 1: odd m
    const int m   = 2 * (((w & 1) << 5) + lane) + par;

    // ---- stage parity-combined, scale-folded rows ----
    {
        const float s = wq[t] * (2.0f * (float)M_PI / 512.0f);
        const float4* x4 = (const float4*)(x + (size_t)t * NP * NC);
        for (int i = tid; i < 2048; i += 128) {
            float4 a = x4[i];
            float4 b = x4[i + 2048];
            const int p = i >> 3, j = i & 7;
            ype[p * 16 + j * 2]     = pk2((a.x + b.x) * s, (a.y + b.y) * s);
            ype[p * 16 + j * 2 + 1] = pk2((a.z + b.z) * s, (a.w + b.w) * s);
            ymo[p * 16 + j * 2]     = pk2((a.x - b.x) * s, (a.y - b.y) * s);
            ymo[p * 16 + j * 2 + 1] = pk2((a.z - b.z) * s, (a.w - b.w) * s);
        }
    }
    __syncthreads();

    // ---- in-place reflection fold: slot q := y_q + y_{256-q},
    //      slot 256-q := y_q - y_{256-q}, q in [1,127]. Race-free (pair-owned).
    {
        const u64 ONE2 = pk2(1.0f, 1.0f), NEG2 = pk2(-1.0f, -1.0f);
        for (int i = tid; i < 4096; i += 128) {
            const int q = (i >> 4) & 127;
            if (q == 0) continue;
            u64* base = sm1 + ((i >> 11) << 12);   // ype or ymo
            const int j  = i & 15;
            const int ia = q * 16 + j, ib = (256 - q) * 16 + j;
            u64 a = base[ia], b = base[ib];
            base[ia] = fma2(b, ONE2, a);
            base[ib] = fma2(b, NEG2, a);
        }
    }
    __syncthreads();

    const u64* yrow = par ? ymo : ype;

    float sd, cd;
    sincosf(-(float)M_PI / 256.0f * (float)m, &sd, &cd);
    u64 CDD = pk2(cd, cd), SDD = pk2(sd, sd), NSD = pk2(-sd, -sd);
    u64 CC = pk2(cd, cd), SS = pk2(sd, sd);    // state at q=1

    u64 aR[16], aI[16];
#pragma unroll
    for (int k = 0; k < 16; k++) { aR[k] = 0ull; aI[k] = 0ull; }

    // R walks slot q (even m) / slot 256-q (odd m); I opposite.
    const u64* pR = yrow + (par ? 255 * 16 : 16);
    const u64* pI = yrow + (par ? 16 : 255 * 16);
    const int  sR = par ? -16 : 16;

#pragma unroll 2
    for (int q = 1; q < 128; q++) {
        const ulonglong2* rR = (const ulonglong2*)pR;
        const ulonglong2* rI = (const ulonglong2*)pI;
#pragma unroll
        for (int k = 0; k < 8; k++) {
            ulonglong2 vR = rR[k];
            ulonglong2 vI = rI[k];
            aR[2 * k]     = fma2(vR.x, CC, aR[2 * k]);
            aR[2 * k + 1] = fma2(vR.y, CC, aR[2 * k + 1]);
            aI[2 * k]     = fma2(vI.x, SS, aI[2 * k]);
            aI[2 * k + 1] = fma2(vI.y, SS, aI[2 * k + 1]);
        }
        u64 t1 = mul2(SS, NSD);
        u64 nC = fma2(CC, CDD, t1);
        u64 t2 = mul2(CC, SDD);
        SS = fma2(SS, CDD, t2);
        CC = nC;
        pR += sR; pI -= sR;
    }

    // ---- edge terms q=0 and q=128 ----
    {
        const ulonglong2* r0 = (const ulonglong2*)yrow;               // y_0
        const ulonglong2* rh = (const ulonglong2*)(yrow + 128 * 16);  // y_128
        const float sg = ((m >> 1) & 1) ? -1.0f : 1.0f;               // (-1)^(m>>1)
        const u64 ONE2 = pk2(1.0f, 1.0f);
        if (!par) {
            const u64 SG = pk2(sg, sg);
#pragma unroll
            for (int k = 0; k < 8; k++) {
                ulonglong2 v0 = r0[k], vh = rh[k];
                aR[2 * k]     = fma2(v0.x, ONE2, aR[2 * k]);
                aR[2 * k + 1] = fma2(v0.y, ONE2, aR[2 * k + 1]);
                aR[2 * k]     = fma2(vh.x, SG, aR[2 * k]);
                aR[2 * k + 1] = fma2(vh.y, SG, aR[2 * k + 1]);
            }
        } else {
            const u64 SG = pk2(-sg, -sg);
#pragma unroll
            for (int k = 0; k < 8; k++) {
                ulonglong2 v0 = r0[k], vh = rh[k];
                aR[2 * k]     = fma2(v0.x, ONE2, aR[2 * k]);
                aR[2 * k + 1] = fma2(v0.y, ONE2, aR[2 * k + 1]);
                aI[2 * k]     = fma2(vh.x, SG, aI[2 * k]);
                aI[2 * k + 1] = fma2(vh.y, SG, aI[2 * k + 1]);
            }
        }
    }

    ulonglong2* fout = (ulonglong2*)&g_F[t][m][0];
#pragma unroll
    for (int k = 0; k < 16; k++) {
        float2 r = upk(aR[k]), i2 = upk(aI[k]);
        fout[k] = make_ulonglong2(pk2(r.x, i2.x), pk2(r.y, i2.y));
    }
}

// ============================================================
// K2: Legendre analysis, theta-parity folded (t<128), m-pair balanced,
// l-range split over blockIdx.y (2) for occupancy.
// grid (64,2), block 256. dynamic smem 64KB: Fp/Fm[128][32] u64.
// ============================================================
__global__ __launch_bounds__(256) void k2_analysis(const float* __restrict__ leg) {
    extern __shared__ u64 sm2[];
    u64* Fp = sm2;               // [128][32]
    u64* Fm = sm2 + 128 * 32;

    const int mp   = blockIdx.x;
    const int lh   = blockIdx.y;
    const int tid  = threadIdx.x;
    const int w    = tid >> 5;
    const int lane = tid & 31;

    for (int half = 0; half < 2; half++) {
        const int m  = half ? (127 - mp) : mp;
        const int nl = NL - m;

        __syncthreads();
        for (int i = tid; i < 128 * 32; i += 256) {
            const int t = i >> 5, c = i & 31;
            float2 a = upk(g_F[t][m][c]);
            float2 b = upk(g_F[255 - t][m][c]);
            Fp[i] = pk2(a.x + b.x, a.y + b.y);
            Fm[i] = pk2(a.x - b.x, a.y - b.y);
        }
        __syncthreads();

        for (int li = (lh * 8 + w) * 4; li < nl; li += 64) {
            u64 acc[4] = {0ull, 0ull, 0ull, 0ull};
            const int lmax = min(4, nl - li);
            const float* bp[4];
#pragma unroll
            for (int k = 0; k < 4; k++) {
                int l = m + li + k; if (l > 127) l = 127;
                bp[k] = leg + ((size_t)l * 255 + (127 + m)) * NT;
            }
#pragma unroll 4
            for (int t = 0; t < 128; t++) {
                u64 fp = Fp[t * 32 + lane];
                u64 fm = Fm[t * 32 + lane];
#pragma unroll
                for (int k = 0; k < 4; k++) {
                    float b = __ldg(bp[k] + t);
                    acc[k] = fma2(pk2(b, b), (k & 1) ? fm : fp, acc[k]);
                }
            }
            for (int k = 0; k < lmax; k++)
                g_flm[m][m + li + k][lane] = acc[k];
        }
    }
}

// ============================================================
// K3: channel mix, +m/-m weight pairs fused (DRAM-bound stream).
// ============================================================
__global__ __launch_bounds__(256) void k3_mix(const float* __restrict__ Wr,
                                              const float* __restrict__ Wi) {
    const int l = blockIdx.x;
    const int m = blockIdx.y;
    if (l < m) return;

    __shared__ float2 sf[32];
    __shared__ float2 red[8][32];
    const int tid = threadIdx.x, w = tid >> 5, lane = tid & 31;

    if (tid < 32) sf[tid] = ((const float2*)&g_flm[m][l][0])[tid];
    __syncthreads();

    const size_t bp = ((size_t)l * 255 + (127 + m)) * 1024;
    const size_t bn = ((size_t)l * 255 + (127 - m)) * 1024;

    float U = 0.0f, V = 0.0f;
#pragma unroll
    for (int k = 0; k < 4; k++) {
        const int c = w * 4 + k;
        const size_t op = bp + (size_t)c * 32 + lane;
        float wr = __ldcs(Wr + op);
        float wi = __ldcs(Wi + op);
        float S, D;
        if (m) {
            const size_t on = bn + (size_t)c * 32 + lane;
            S = wr + __ldcs(Wr + on);
            D = __ldcs(Wi + on) - wi;
        } else {
            S = wr; D = -wi;
        }
        const float fr = sf[c].x, fi = sf[c].y;
        U += fr * S; U += fi * D;
        V += fr * D; V -= fi * S;
    }
    red[w][lane] = make_float2(U, V);
    __syncthreads();
    if (w == 0) {
        float2 a = red[0][lane];
#pragma unroll
        for (int k = 1; k < 8; k++) { a.x += red[k][lane].x; a.y += red[k][lane].y; }
        g_uv[m][l][lane] = pk2(a.x, a.y);
    }
}

// ============================================================
// K4: Legendre synthesis, all-smem inner loop (LDS only).
// grid (128 m, 4 tg), block 256. dynamic smem 64KB.
// ============================================================
__global__ __launch_bounds__(256) void k4_synth(const float* __restrict__ leg) {
    extern __shared__ u64 sm4[];
    u64* suv = sm4;              // [128][32]
    u64* sPd = sm4 + 128 * 32;   // [128][32]

    const int m   = blockIdx.x;
    const int tg  = blockIdx.y;
    const int nl  = NL - m;
    const int nlp = (nl + 3) & ~3;
    const int tid = threadIdx.x, w = tid >> 5, lane = tid & 31;
    const int tb  = w * 4;

    const u64* uvp = &g_uv[m][m][0];
    for (int i = tid; i < nlp * 32; i += 256)
        suv[i] = (i < nl * 32) ? uvp[i] : 0ull;
    const float* Pp = leg + ((size_t)m * 255 + (127 + m)) * NT + tg * 32;
    for (int i = tid; i < nlp * 32; i += 256) {
        const int il = i >> 5, tt = i & 31;
        float v = (il < nl) ? __ldg(Pp + (size_t)il * (255 * NT) + tt) : 0.0f;
        sPd[i] = pk2(v, v);
    }
    __syncthreads();

    u64 E[4] = {0ull, 0ull, 0ull, 0ull};
    u64 O[4] = {0ull, 0ull, 0ull, 0ull};

#pragma unroll 2
    for (int il = 0; il < nlp; il += 2) {
        const u64 uv0 = suv[il * 32 + lane];
        const u64 uv1 = suv[(il + 1) * 32 + lane];
        const ulonglong2* p0 = (const ulonglong2*)(sPd + il * 32 + tb);
        const ulonglong2* p1 = (const ulonglong2*)(sPd + (il + 1) * 32 + tb);
        ulonglong2 pa = p0[0], pb = p0[1];
        ulonglong2 pc = p1[0], pd = p1[1];
        E[0] = fma2(pa.x, uv0, E[0]);
        E[1] = fma2(pa.y, uv0, E[1]);
        E[2] = fma2(pb.x, uv0, E[2]);
        E[3] = fma2(pb.y, uv0, E[3]);
        O[0] = fma2(pc.x, uv1, O[0]);
        O[1] = fma2(pc.y, uv1, O[1]);
        O[2] = fma2(pd.x, uv1, O[2]);
        O[3] = fma2(pd.y, uv1, O[3]);
    }

#pragma unroll
    for (int j = 0; j < 4; j++) {
        const int t = tg * 32 + tb + j;
        float2 e = upk(E[j]), o2 = upk(O[j]);
        g_AB[t][m][lane]       = pk2(e.x + o2.x, e.y + o2.y);
        g_AB[255 - t][m][lane] = pk2(e.x - o2.x, e.y - o2.y);
    }
}

// ============================================================
// K5: inverse transform, m-parity + p-reflection folded.
// p in [0,127] produces p, 256-p, 256+p, 512-p (guard p=0).
// grid 256 (t), block 256 = 128 p x 2 o-groups.
// ============================================================
__global__ __launch_bounds__(256) void k5_idft(float* __restrict__ out) {
    __shared__ u64 sAB[128 * 32];    // 32 KB
    const int t   = blockIdx.x;
    const int tid = threadIdx.x;
    const int p   = tid & 127;
    const int ob  = (tid >> 7) * 16;

    for (int i = tid; i < 128 * 32; i += 256)
        sAB[i] = ((const u64*)&g_AB[t][0][0])[i];
    __syncthreads();

    u64 E[16], O[16];
#pragma unroll
    for (int k = 0; k < 16; k++) { E[k] = 0ull; O[k] = 0ull; }

    float sd, cd;
    sincosf(((float)M_PI / 256.0f) * (float)p, &sd, &cd);
    u64 CDD = pk2(cd, cd);
    u64 P1 = pk2(-sd, sd), P2 = pk2(sd, -sd);
    u64 cs = pk2(1.0f, 0.0f), sc = pk2(0.0f, 1.0f);

#pragma unroll 2
    for (int m = 0; m < 128; m += 2) {
        const ulonglong2* r0 = (const ulonglong2*)(sAB + m * 32 + ob);
#pragma unroll
        for (int k = 0; k < 8; k++) {
            ulonglong2 v = r0[k];
            E[2 * k]     = fma2(v.x, cs, E[2 * k]);
            E[2 * k + 1] = fma2(v.y, cs, E[2 * k + 1]);
        }
        { u64 t1 = mul2(sc, P1); u64 nc = fma2(cs, CDD, t1);
          u64 t2 = mul2(cs, P2); sc = fma2(sc, CDD, t2); cs = nc; }

        const ulonglong2* r1 = (const ulonglong2*)(sAB + (m + 1) * 32 + ob);
#pragma unroll
        for (int k = 0; k < 8; k++) {
            ulonglong2 v = r1[k];
            O[2 * k]     = fma2(v.x, cs, O[2 * k]);
            O[2 * k + 1] = fma2(v.y, cs, O[2 * k + 1]);
        }
        { u64 t1 = mul2(sc, P1); u64 nc = fma2(cs, CDD, t1);
          u64 t2 = mul2(cs, P2); sc = fma2(sc, CDD, t2); cs = nc; }
    }

#pragma unroll
    for (int k = 0; k < 16; k++) {
        float2 e = upk(E[k]), o2 = upk(O[k]);
        const float s1 = e.x + e.y, s2 = e.x - e.y;
        const float d1 = o2.x + o2.y, d2 = o2.x - o2.y;
        const size_t base = ((size_t)(ob + k) * NT + t) * NP;
        out[base + p]       = s1 + d1;
        out[base + 256 + p] = s1 - d1;
        out[base + 256 - p] = s2 - d2;
        if (p) out[base + 512 - p] = s2 + d2;
    }
}

// ============================================================
// K5b: columns p=128 and p=384.
// out[128] = (S0-S2) + (T1-T3); out[384] = (S0-S2) - (T1-T3)
// where S_r = sum_{m=r mod 4} A_m (r even), T_r = sum B_m (r odd).
// grid 256 (t), block 128 = 4 warps (m residue) x 32 lanes (o).
// ============================================================
__global__ __launch_bounds__(128) void k5b_edge(float* __restrict__ out) {
    __shared__ float red[4][32];
    const int t = blockIdx.x;
    const int w = threadIdx.x >> 5, lane = threadIdx.x & 31;

    float acc = 0.0f;
#pragma unroll 8
    for (int k = 0; k < 32; k++) {
        float2 v = upk(g_AB[t][w + 4 * k][lane]);
        acc += (w & 1) ? v.y : v.x;
    }
    red[w][lane] = acc;
    __syncthreads();
    if (w == 0) {
        const float U = red[0][lane] - red[2][lane];
        const float V = red[1][lane] - red[3][lane];
        const size_t base = ((size_t)lane * NT + t) * NP;
        out[base + 128] = U + V;
        out[base + 384] = U - V;
    }
}

// ============================================================
extern "C" void kernel_launch(void* const* d_in, const int* in_sizes, int n_in,
                              void* d_out, int out_size) {
    const float* x   = (const float*)d_in[0];
    const float* Wr  = (const float*)d_in[1];
    const float* Wi  = (const float*)d_in[2];
    const float* leg = (const float*)d_in[3];
    const float* wq  = (const float*)d_in[4];
    float* out = (float*)d_out;

    cudaFuncSetAttribute(k1_dft,      cudaFuncAttributeMaxDynamicSharedMemorySize, 65536);
    cudaFuncSetAttribute(k2_analysis, cudaFuncAttributeMaxDynamicSharedMemorySize, 65536);
    cudaFuncSetAttribute(k4_synth,    cudaFuncAttributeMaxDynamicSharedMemorySize, 65536);

    k1_dft<<<256, 128, 65536>>>(x, wq);
    k2_analysis<<<dim3(64, 2), 256, 65536>>>(leg);
    k3_mix<<<dim3(128, 128), 256>>>(Wr, Wi);
    k4_synth<<<dim3(128, 4), 256, 65536>>>(leg);
    k5_idft<<<256, 256>>>(out);
    k5b_edge<<<256, 128>>>(out);
}

// round 9
// speedup vs baseline: 2.2444x; 1.0329x over previous
#include <cuda_runtime.h>
#include <math.h>

#define NT 256   // ntheta
#define NP 512   // nphi
#define NC 32    // channels
#define NL 128   // L

typedef unsigned long long u64;

// ---------- packed f32x2 helpers (sm_103a FFMA2) ----------
__device__ __forceinline__ u64 pk2(float a, float b) {
    u64 r; asm("mov.b64 %0,{%1,%2};" : "=l"(r) : "f"(a), "f"(b)); return r;
}
__device__ __forceinline__ float2 upk(u64 v) {
    float2 f; asm("mov.b64 {%0,%1},%2;" : "=f"(f.x), "=f"(f.y) : "l"(v)); return f;
}
__device__ __forceinline__ u64 fma2(u64 a, u64 b, u64 c) {
    u64 d; asm("fma.rn.f32x2 %0,%1,%2,%3;" : "=l"(d) : "l"(a), "l"(b), "l"(c)); return d;
}
__device__ __forceinline__ u64 mul2(u64 a, u64 b) {
    u64 d; asm("mul.rn.f32x2 %0,%1,%2;" : "=l"(d) : "l"(a), "l"(b)); return d;
}
// ---------- PDL (programmatic dependent launch) ----------
__device__ __forceinline__ void gdc_launch() {
    asm volatile("griddepcontrol.launch_dependents;" ::: "memory");
}
__device__ __forceinline__ void gdc_wait() {
    asm volatile("griddepcontrol.wait;" ::: "memory");
}

// ---------- static device scratch ----------
__device__ u64 g_F  [NT][NL][NC];   // (re,im) of F[t][m][c], wq*2pi/512 folded in
__device__ u64 g_flm[NL][NL][NC];   // [m][l][c]; valid only l>=m
__device__ u64 g_uv [NL][NL][NC];   // [m][l][o]; valid only l>=m
__device__ u64 g_AB [NT][NL][NC];   // [t][m][o] (A,B)

// ============================================================
// K1: forward DFT over phi, radix-2 + q-reflection folded.
// grid 256 (t), block 128 (m). dynamic smem 64KB.
// ============================================================
__global__ __launch_bounds__(128) void k1_dft(const float* __restrict__ x,
                                              const float* __restrict__ wq) {
    gdc_launch();
    extern __shared__ u64 sm1[];
    u64* ype = sm1;              // [256][16]
    u64* ymo = sm1 + 4096;       // [256][16]

    const int t   = blockIdx.x;
    const int tid = threadIdx.x;
    const int w   = tid >> 5;
    const int lane = tid & 31;
    const int par = w >> 1;                       // 0: even m, 1: odd m
    const int m   = 2 * (((w & 1) << 5) + lane) + par;

    {
        const float s = wq[t] * (2.0f * (float)M_PI / 512.0f);
        const float4* x4 = (const float4*)(x + (size_t)t * NP * NC);
        for (int i = tid; i < 2048; i += 128) {
            float4 a = x4[i];
            float4 b = x4[i + 2048];
            const int p = i >> 3, j = i & 7;
            ype[p * 16 + j * 2]     = pk2((a.x + b.x) * s, (a.y + b.y) * s);
            ype[p * 16 + j * 2 + 1] = pk2((a.z + b.z) * s, (a.w + b.w) * s);
            ymo[p * 16 + j * 2]     = pk2((a.x - b.x) * s, (a.y - b.y) * s);
            ymo[p * 16 + j * 2 + 1] = pk2((a.z - b.z) * s, (a.w - b.w) * s);
        }
    }
    __syncthreads();

    {
        const u64 ONE2 = pk2(1.0f, 1.0f), NEG2 = pk2(-1.0f, -1.0f);
        for (int i = tid; i < 4096; i += 128) {
            const int q = (i >> 4) & 127;
            if (q == 0) continue;
            u64* base = sm1 + ((i >> 11) << 12);
            const int j  = i & 15;
            const int ia = q * 16 + j, ib = (256 - q) * 16 + j;
            u64 a = base[ia], b = base[ib];
            base[ia] = fma2(b, ONE2, a);
            base[ib] = fma2(b, NEG2, a);
        }
    }
    __syncthreads();

    const u64* yrow = par ? ymo : ype;

    float sd, cd;
    sincosf(-(float)M_PI / 256.0f * (float)m, &sd, &cd);
    u64 CDD = pk2(cd, cd), SDD = pk2(sd, sd), NSD = pk2(-sd, -sd);
    u64 CC = pk2(cd, cd), SS = pk2(sd, sd);    // state at q=1

    u64 aR[16], aI[16];
#pragma unroll
    for (int k = 0; k < 16; k++) { aR[k] = 0ull; aI[k] = 0ull; }

    const u64* pR = yrow + (par ? 255 * 16 : 16);
    const u64* pI = yrow + (par ? 16 : 255 * 16);
    const int  sR = par ? -16 : 16;

#pragma unroll 2
    for (int q = 1; q < 128; q++) {
        const ulonglong2* rR = (const ulonglong2*)pR;
        const ulonglong2* rI = (const ulonglong2*)pI;
#pragma unroll
        for (int k = 0; k < 8; k++) {
            ulonglong2 vR = rR[k];
            ulonglong2 vI = rI[k];
            aR[2 * k]     = fma2(vR.x, CC, aR[2 * k]);
            aR[2 * k + 1] = fma2(vR.y, CC, aR[2 * k + 1]);
            aI[2 * k]     = fma2(vI.x, SS, aI[2 * k]);
            aI[2 * k + 1] = fma2(vI.y, SS, aI[2 * k + 1]);
        }
        u64 t1 = mul2(SS, NSD);
        u64 nC = fma2(CC, CDD, t1);
        u64 t2 = mul2(CC, SDD);
        SS = fma2(SS, CDD, t2);
        CC = nC;
        pR += sR; pI -= sR;
    }

    {
        const ulonglong2* r0 = (const ulonglong2*)yrow;
        const ulonglong2* rh = (const ulonglong2*)(yrow + 128 * 16);
        const float sg = ((m >> 1) & 1) ? -1.0f : 1.0f;
        const u64 ONE2 = pk2(1.0f, 1.0f);
        if (!par) {
            const u64 SG = pk2(sg, sg);
#pragma unroll
            for (int k = 0; k < 8; k++) {
                ulonglong2 v0 = r0[k], vh = rh[k];
                aR[2 * k]     = fma2(v0.x, ONE2, aR[2 * k]);
                aR[2 * k + 1] = fma2(v0.y, ONE2, aR[2 * k + 1]);
                aR[2 * k]     = fma2(vh.x, SG, aR[2 * k]);
                aR[2 * k + 1] = fma2(vh.y, SG, aR[2 * k + 1]);
            }
        } else {
            const u64 SG = pk2(-sg, -sg);
#pragma unroll
            for (int k = 0; k < 8; k++) {
                ulonglong2 v0 = r0[k], vh = rh[k];
                aR[2 * k]     = fma2(v0.x, ONE2, aR[2 * k]);
                aR[2 * k + 1] = fma2(v0.y, ONE2, aR[2 * k + 1]);
                aI[2 * k]     = fma2(vh.x, SG, aI[2 * k]);
                aI[2 * k + 1] = fma2(vh.y, SG, aI[2 * k + 1]);
            }
        }
    }

    ulonglong2* fout = (ulonglong2*)&g_F[t][m][0];
#pragma unroll
    for (int k = 0; k < 16; k++) {
        float2 r = upk(aR[k]), i2 = upk(aI[k]);
        fout[k] = make_ulonglong2(pk2(r.x, i2.x), pk2(r.y, i2.y));
    }
}

// ============================================================
// K2: Legendre analysis (PDL secondary of K1, primary of K3).
// grid (64,2), block 256. dynamic smem 64KB.
// ============================================================
__global__ __launch_bounds__(256) void k2_analysis(const float* __restrict__ leg) {
    gdc_launch();
    extern __shared__ u64 sm2[];
    u64* Fp = sm2;               // [128][32]
    u64* Fm = sm2 + 128 * 32;

    const int mp   = blockIdx.x;
    const int lh   = blockIdx.y;
    const int tid  = threadIdx.x;
    const int w    = tid >> 5;
    const int lane = tid & 31;

    gdc_wait();   // g_F ready

    for (int half = 0; half < 2; half++) {
        const int m  = half ? (127 - mp) : mp;
        const int nl = NL - m;

        __syncthreads();
        for (int i = tid; i < 128 * 32; i += 256) {
            const int t = i >> 5, c = i & 31;
            float2 a = upk(g_F[t][m][c]);
            float2 b = upk(g_F[255 - t][m][c]);
            Fp[i] = pk2(a.x + b.x, a.y + b.y);
            Fm[i] = pk2(a.x - b.x, a.y - b.y);
        }
        __syncthreads();

        for (int li = (lh * 8 + w) * 4; li < nl; li += 64) {
            u64 acc[4] = {0ull, 0ull, 0ull, 0ull};
            const int lmax = min(4, nl - li);
            const float* bp[4];
#pragma unroll
            for (int k = 0; k < 4; k++) {
                int l = m + li + k; if (l > 127) l = 127;
                bp[k] = leg + ((size_t)l * 255 + (127 + m)) * NT;
            }
#pragma unroll 4
            for (int t = 0; t < 128; t++) {
                u64 fp = Fp[t * 32 + lane];
                u64 fm = Fm[t * 32 + lane];
#pragma unroll
                for (int k = 0; k < 4; k++) {
                    float b = __ldg(bp[k] + t);
                    acc[k] = fma2(pk2(b, b), (k & 1) ? fm : fp, acc[k]);
                }
            }
            for (int k = 0; k < lmax; k++)
                g_flm[m][m + li + k][lane] = acc[k];
        }
    }
}

// ============================================================
// K3: channel mix. PDL: weight loads issued BEFORE the grid-dep wait
// (independent of K2) so the DRAM stream overlaps K2.
// ============================================================
__global__ __launch_bounds__(256) void k3_mix(const float* __restrict__ Wr,
                                              const float* __restrict__ Wi) {
    gdc_launch();
    const int l = blockIdx.x;
    const int m = blockIdx.y;
    if (l < m) return;

    __shared__ float2 sf[32];
    __shared__ float2 red[8][32];
    const int tid = threadIdx.x, w = tid >> 5, lane = tid & 31;

    const size_t bp = ((size_t)l * 255 + (127 + m)) * 1024;
    const size_t bn = ((size_t)l * 255 + (127 - m)) * 1024;

    // ---- prefetch weights (independent of K2) ----
    float S[4], D[4];
#pragma unroll
    for (int k = 0; k < 4; k++) {
        const int c = w * 4 + k;
        const size_t op = bp + (size_t)c * 32 + lane;
        float wr = __ldcs(Wr + op);
        float wi = __ldcs(Wi + op);
        if (m) {
            const size_t on = bn + (size_t)c * 32 + lane;
            S[k] = wr + __ldcs(Wr + on);
            D[k] = __ldcs(Wi + on) - wi;
        } else {
            S[k] = wr; D[k] = -wi;
        }
    }

    gdc_wait();   // g_flm ready

    if (tid < 32) sf[tid] = ((const float2*)&g_flm[m][l][0])[tid];
    __syncthreads();

    float U = 0.0f, V = 0.0f;
#pragma unroll
    for (int k = 0; k < 4; k++) {
        const int c = w * 4 + k;
        const float fr = sf[c].x, fi = sf[c].y;
        U += fr * S[k]; U += fi * D[k];
        V += fr * D[k]; V -= fi * S[k];
    }
    red[w][lane] = make_float2(U, V);
    __syncthreads();
    if (w == 0) {
        float2 a = red[0][lane];
#pragma unroll
        for (int k = 1; k < 8; k++) { a.x += red[k][lane].x; a.y += red[k][lane].y; }
        g_uv[m][l][lane] = pk2(a.x, a.y);
    }
}

// ============================================================
// K4: Legendre synthesis, all-smem inner loop. PDL: leg staging
// (independent) happens before the grid-dep wait, overlapping K3.
// grid (128 m, 4 tg), block 256. dynamic smem 64KB.
// ============================================================
__global__ __launch_bounds__(256) void k4_synth(const float* __restrict__ leg) {
    gdc_launch();
    extern __shared__ u64 sm4[];
    u64* suv = sm4;              // [128][32]
    u64* sPd = sm4 + 128 * 32;   // [128][32]

    const int m   = blockIdx.x;
    const int tg  = blockIdx.y;
    const int nl  = NL - m;
    const int nlp = (nl + 3) & ~3;
    const int tid = threadIdx.x, w = tid >> 5, lane = tid & 31;
    const int tb  = w * 4;

    // ---- stage P (independent of K3) ----
    const float* Pp = leg + ((size_t)m * 255 + (127 + m)) * NT + tg * 32;
    for (int i = tid; i < nlp * 32; i += 256) {
        const int il = i >> 5, tt = i & 31;
        float v = (il < nl) ? __ldg(Pp + (size_t)il * (255 * NT) + tt) : 0.0f;
        sPd[i] = pk2(v, v);
    }

    gdc_wait();   // g_uv ready

    const u64* uvp = &g_uv[m][m][0];
    for (int i = tid; i < nlp * 32; i += 256)
        suv[i] = (i < nl * 32) ? uvp[i] : 0ull;
    __syncthreads();

    u64 E[4] = {0ull, 0ull, 0ull, 0ull};
    u64 O[4] = {0ull, 0ull, 0ull, 0ull};

#pragma unroll 2
    for (int il = 0; il < nlp; il += 2) {
        const u64 uv0 = suv[il * 32 + lane];
        const u64 uv1 = suv[(il + 1) * 32 + lane];
        const ulonglong2* p0 = (const ulonglong2*)(sPd + il * 32 + tb);
        const ulonglong2* p1 = (const ulonglong2*)(sPd + (il + 1) * 32 + tb);
        ulonglong2 pa = p0[0], pb = p0[1];
        ulonglong2 pc = p1[0], pd = p1[1];
        E[0] = fma2(pa.x, uv0, E[0]);
        E[1] = fma2(pa.y, uv0, E[1]);
        E[2] = fma2(pb.x, uv0, E[2]);
        E[3] = fma2(pb.y, uv0, E[3]);
        O[0] = fma2(pc.x, uv1, O[0]);
        O[1] = fma2(pc.y, uv1, O[1]);
        O[2] = fma2(pd.x, uv1, O[2]);
        O[3] = fma2(pd.y, uv1, O[3]);
    }

#pragma unroll
    for (int j = 0; j < 4; j++) {
        const int t = tg * 32 + tb + j;
        float2 e = upk(E[j]), o2 = upk(O[j]);
        g_AB[t][m][lane]       = pk2(e.x + o2.x, e.y + o2.y);
        g_AB[255 - t][m][lane] = pk2(e.x - o2.x, e.y - o2.y);
    }
}

// ============================================================
// K5: inverse transform, m-parity + p-reflection folded, with the
// p=128/384 edge columns FUSED (uses the already-staged sAB).
// grid 256 (t), block 256 = 128 p x 2 o-groups.
// ============================================================
__global__ __launch_bounds__(256) void k5_idft(float* __restrict__ out) {
    __shared__ u64 sAB[128 * 32];    // 32 KB
    __shared__ float redu[8][32], redv[8][32];
    const int t   = blockIdx.x;
    const int tid = threadIdx.x;
    const int p   = tid & 127;
    const int ob  = (tid >> 7) * 16;

    gdc_wait();   // g_AB ready

    for (int i = tid; i < 128 * 32; i += 256)
        sAB[i] = ((const u64*)&g_AB[t][0][0])[i];
    __syncthreads();

    u64 E[16], O[16];
#pragma unroll
    for (int k = 0; k < 16; k++) { E[k] = 0ull; O[k] = 0ull; }

    float sd, cd;
    sincosf(((float)M_PI / 256.0f) * (float)p, &sd, &cd);
    u64 CDD = pk2(cd, cd);
    u64 P1 = pk2(-sd, sd), P2 = pk2(sd, -sd);
    u64 cs = pk2(1.0f, 0.0f), sc = pk2(0.0f, 1.0f);

#pragma unroll 2
    for (int m = 0; m < 128; m += 2) {
        const ulonglong2* r0 = (const ulonglong2*)(sAB + m * 32 + ob);
#pragma unroll
        for (int k = 0; k < 8; k++) {
            ulonglong2 v = r0[k];
            E[2 * k]     = fma2(v.x, cs, E[2 * k]);
            E[2 * k + 1] = fma2(v.y, cs, E[2 * k + 1]);
        }
        { u64 t1 = mul2(sc, P1); u64 nc = fma2(cs, CDD, t1);
          u64 t2 = mul2(cs, P2); sc = fma2(sc, CDD, t2); cs = nc; }

        const ulonglong2* r1 = (const ulonglong2*)(sAB + (m + 1) * 32 + ob);
#pragma unroll
        for (int k = 0; k < 8; k++) {
            ulonglong2 v = r1[k];
            O[2 * k]     = fma2(v.x, cs, O[2 * k]);
            O[2 * k + 1] = fma2(v.y, cs, O[2 * k + 1]);
        }
        { u64 t1 = mul2(sc, P1); u64 nc = fma2(cs, CDD, t1);
          u64 t2 = mul2(cs, P2); sc = fma2(sc, CDD, t2); cs = nc; }
    }

#pragma unroll
    for (int k = 0; k < 16; k++) {
        float2 e = upk(E[k]), o2 = upk(O[k]);
        const float s1 = e.x + e.y, s2 = e.x - e.y;
        const float d1 = o2.x + o2.y, d2 = o2.x - o2.y;
        const size_t base = ((size_t)(ob + k) * NT + t) * NP;
        out[base + p]       = s1 + d1;
        out[base + 256 + p] = s1 - d1;
        out[base + 256 - p] = s2 - d2;
        if (p) out[base + 512 - p] = s2 + d2;
    }

    // ---- fused edge columns p=128, 384 ----
    {
        const int seg = tid >> 5, o = tid & 31;
        float u = 0.0f, v = 0.0f;
#pragma unroll
        for (int k = 0; k < 16; k++) {
            const int m = seg * 16 + k;
            float2 val = upk(sAB[m * 32 + o]);
            if (m & 1) v += (m & 2) ? -val.y : val.y;
            else       u += (m & 2) ? -val.x : val.x;
        }
        redu[seg][o] = u; redv[seg][o] = v;
        __syncthreads();
        if (seg == 0) {
            float U = 0.0f, V = 0.0f;
#pragma unroll
            for (int s = 0; s < 8; s++) { U += redu[s][o]; V += redv[s][o]; }
            const size_t base = ((size_t)o * NT + t) * NP;
            out[base + 128] = U + V;
            out[base + 384] = U - V;
        }
    }
}

// ============================================================
extern "C" void kernel_launch(void* const* d_in, const int* in_sizes, int n_in,
                              void* d_out, int out_size) {
    const float* x   = (const float*)d_in[0];
    const float* Wr  = (const float*)d_in[1];
    const float* Wi  = (const float*)d_in[2];
    const float* leg = (const float*)d_in[3];
    const float* wq  = (const float*)d_in[4];
    float* out = (float*)d_out;

    cudaFuncSetAttribute(k1_dft,      cudaFuncAttributeMaxDynamicSharedMemorySize, 65536);
    cudaFuncSetAttribute(k2_analysis, cudaFuncAttributeMaxDynamicSharedMemorySize, 65536);
    cudaFuncSetAttribute(k4_synth,    cudaFuncAttributeMaxDynamicSharedMemorySize, 65536);

    cudaLaunchAttribute pdl[1];
    pdl[0].id = cudaLaunchAttributeProgrammaticStreamSerialization;
    pdl[0].val.programmaticStreamSerializationAllowed = 1;

    k1_dft<<<256, 128, 65536>>>(x, wq);

    {
        cudaLaunchConfig_t c{};
        c.gridDim = dim3(64, 2); c.blockDim = dim3(256);
        c.dynamicSmemBytes = 65536; c.stream = 0;
        c.attrs = pdl; c.numAttrs = 1;
        cudaLaunchKernelEx(&c, k2_analysis, leg);
    }
    {
        cudaLaunchConfig_t c{};
        c.gridDim = dim3(128, 128); c.blockDim = dim3(256);
        c.dynamicSmemBytes = 0; c.stream = 0;
        c.attrs = pdl; c.numAttrs = 1;
        cudaLaunchKernelEx(&c, k3_mix, Wr, Wi);
    }
    {
        cudaLaunchConfig_t c{};
        c.gridDim = dim3(128, 4); c.blockDim = dim3(256);
        c.dynamicSmemBytes = 65536; c.stream = 0;
        c.attrs = pdl; c.numAttrs = 1;
        cudaLaunchKernelEx(&c, k4_synth, leg);
    }
    {
        cudaLaunchConfig_t c{};
        c.gridDim = dim3(256); c.blockDim = dim3(256);
        c.dynamicSmemBytes = 0; c.stream = 0;
        c.attrs = pdl; c.numAttrs = 1;
        cudaLaunchKernelEx(&c, k5_idft, out);
    }
}